// round 1
// baseline (speedup 1.0000x reference)
#include <cuda_runtime.h>

#define NN 50000
#define EE 800000
#define HC 256

// ---------------- scratch (device globals; no allocation allowed) ----------------
__device__ float g_xs[NN * HC];     // xs of current layer (x@W)
__device__ float g_hpre[NN * HC];   // aggregated pre-BN output of current layer
__device__ float g_h1[NN * HC];     // BN-ReLU(layer1) -> input to GEMM2
__device__ float g_as[NN * 4];
__device__ float g_ad[NN * 4];
__device__ float g_ae1[EE * 4];
__device__ float g_ae2[EE * 4];
__device__ int   g_deg[NN];
__device__ int   g_offs[NN + 1];
__device__ int   g_cursor[NN];
__device__ int   g_bsum[256];
__device__ int   g_bbase[257];
__device__ int   g_csrc[EE];
__device__ int   g_ceid[EE];
__device__ float g_ve1[64];         // [16,4]
__device__ float g_ve2[64];
__device__ float g_stats[1024];     // layer1: [0,512), layer2: [512,1024)

__device__ __forceinline__ float lrelu(float x) { return fmaxf(x, 0.2f * x); }

// ---------------- setup kernels ----------------
__global__ void k_zero() {
    int i = blockIdx.x * blockDim.x + threadIdx.x;
    if (i < NN) g_deg[i] = 0;
    if (i < 1024) g_stats[i] = 0.f;
}

// Ve[j][h] = sum_c We[j, h*64+c] * atte[h, c]   (collapses ee = ea2@We entirely)
__global__ void k_ve(const float* __restrict__ We1, const float* __restrict__ at1,
                     const float* __restrict__ We2, const float* __restrict__ at2) {
    int t = threadIdx.x;            // 128 threads
    int which = t >> 6;
    int u = t & 63;
    int j = u >> 2, h = u & 3;
    const float* We = which ? We2 : We1;
    const float* at = which ? at2 : at1;
    float s = 0.f;
    #pragma unroll 8
    for (int c = 0; c < 64; c++) s += We[j * HC + h * 64 + c] * at[h * 64 + c];
    if (which) g_ve2[u] = s; else g_ve1[u] = s;
}

// per-edge a_e for both layers + degree histogram
__global__ void k_edge(const float* __restrict__ eattr, const int* __restrict__ dst) {
    int e = blockIdx.x * blockDim.x + threadIdx.x;
    if (e >= EE) return;
    const float4* p = (const float4*)(eattr + (size_t)e * 16);
    float4 a = p[0], b = p[1], c = p[2], d = p[3];
    float v[16] = {a.x,a.y,a.z,a.w, b.x,b.y,b.z,b.w, c.x,c.y,c.z,c.w, d.x,d.y,d.z,d.w};
    float o1[4] = {0,0,0,0}, o2[4] = {0,0,0,0};
    #pragma unroll
    for (int j = 0; j < 16; j++) {
        #pragma unroll
        for (int h = 0; h < 4; h++) {
            o1[h] += v[j] * g_ve1[j * 4 + h];
            o2[h] += v[j] * g_ve2[j * 4 + h];
        }
    }
    *(float4*)(g_ae1 + (size_t)e * 4) = make_float4(o1[0], o1[1], o1[2], o1[3]);
    *(float4*)(g_ae2 + (size_t)e * 4) = make_float4(o2[0], o2[1], o2[2], o2[3]);
    atomicAdd(&g_deg[dst[e]], 1);
}

// ------------- 3-kernel exclusive scan of deg -> offs, cursor -------------
__global__ void k_scan1() {                         // 196 blocks x 256
    __shared__ int sh[256];
    int b = blockIdx.x, t = threadIdx.x;
    int i = b * 256 + t;
    sh[t] = (i < NN) ? g_deg[i] : 0;
    __syncthreads();
    for (int o = 128; o; o >>= 1) { if (t < o) sh[t] += sh[t + o]; __syncthreads(); }
    if (t == 0) g_bsum[b] = sh[0];
}

__global__ void k_scan2(int nb) {                   // 1 block x 256
    __shared__ int sh[256];
    int t = threadIdx.x;
    sh[t] = (t < nb) ? g_bsum[t] : 0;
    __syncthreads();
    for (int o = 1; o < 256; o <<= 1) {
        int v = (t >= o) ? sh[t - o] : 0;
        __syncthreads();
        sh[t] += v;
        __syncthreads();
    }
    g_bbase[t + 1] = sh[t];
    if (t == 0) { g_bbase[0] = 0; g_offs[NN] = EE; }
}

__global__ void k_scan3() {                         // 196 blocks x 256
    __shared__ int sh[256];
    int b = blockIdx.x, t = threadIdx.x;
    int i = b * 256 + t;
    int d = (i < NN) ? g_deg[i] : 0;
    sh[t] = d;
    __syncthreads();
    for (int o = 1; o < 256; o <<= 1) {
        int v = (t >= o) ? sh[t - o] : 0;
        __syncthreads();
        sh[t] += v;
        __syncthreads();
    }
    if (i < NN) {
        int off = g_bbase[b] + sh[t] - d;
        g_offs[i] = off;
        g_cursor[i] = off;
    }
}

__global__ void k_fill(const int* __restrict__ src, const int* __restrict__ dst) {
    int e = blockIdx.x * blockDim.x + threadIdx.x;
    if (e >= EE) return;
    int pos = atomicAdd(&g_cursor[dst[e]], 1);
    g_csrc[pos] = src[e];
    g_ceid[pos] = e;
}

// ---------------- SGEMM: C[M,256] = A[M,K] @ B[K,256], fp32, 128x128x8 tiled ----------------
__global__ void __launch_bounds__(256)
k_sgemm(const float* __restrict__ Aext, const float* __restrict__ B, int M, int K) {
    const float* A = Aext ? Aext : g_h1;
    __shared__ float As[8 * 132];   // stride 132 kills store bank conflicts
    __shared__ float Bs[8 * 128];
    int tid = threadIdx.x;
    int tx = tid & 15, ty = tid >> 4;
    int rowBlk = blockIdx.y * 128, colBlk = blockIdx.x * 128;
    int aRow = tid >> 1;
    int aCol = (tid & 1) * 4;
    int bRow = tid >> 5;
    int bCol = (tid & 31) * 4;
    bool aValid = (rowBlk + aRow) < M;
    const float* Ap = A + (size_t)(rowBlk + aRow) * K + aCol;
    const float* Bp = B + (size_t)bRow * 256 + colBlk + bCol;
    float acc[8][8];
    #pragma unroll
    for (int i = 0; i < 8; i++)
        #pragma unroll
        for (int j = 0; j < 8; j++) acc[i][j] = 0.f;

    for (int k0 = 0; k0 < K; k0 += 8) {
        float4 av = aValid ? *(const float4*)(Ap + k0) : make_float4(0, 0, 0, 0);
        As[(aCol + 0) * 132 + aRow] = av.x;
        As[(aCol + 1) * 132 + aRow] = av.y;
        As[(aCol + 2) * 132 + aRow] = av.z;
        As[(aCol + 3) * 132 + aRow] = av.w;
        *(float4*)(Bs + bRow * 128 + bCol) = *(const float4*)(Bp + (size_t)k0 * 256);
        __syncthreads();
        #pragma unroll
        for (int k = 0; k < 8; k++) {
            float ra[8], rb[8];
            *(float4*)(ra)     = *(const float4*)(As + k * 132 + ty * 8);
            *(float4*)(ra + 4) = *(const float4*)(As + k * 132 + ty * 8 + 4);
            *(float4*)(rb)     = *(const float4*)(Bs + k * 128 + tx * 8);
            *(float4*)(rb + 4) = *(const float4*)(Bs + k * 128 + tx * 8 + 4);
            #pragma unroll
            for (int i = 0; i < 8; i++)
                #pragma unroll
                for (int j = 0; j < 8; j++)
                    acc[i][j] = fmaf(ra[i], rb[j], acc[i][j]);
        }
        __syncthreads();
    }
    #pragma unroll
    for (int i = 0; i < 8; i++) {
        int r = rowBlk + ty * 8 + i;
        if (r < M) {
            float* Cp = g_xs + (size_t)r * 256 + colBlk + tx * 8;
            *(float4*)(Cp)     = make_float4(acc[i][0], acc[i][1], acc[i][2], acc[i][3]);
            *(float4*)(Cp + 4) = make_float4(acc[i][4], acc[i][5], acc[i][6], acc[i][7]);
        }
    }
}

// ---------------- per-node attention dots a_s, a_d (warp per node) ----------------
__global__ void k_attdot(const float* __restrict__ atts, const float* __restrict__ attd) {
    int w = (blockIdx.x * blockDim.x + threadIdx.x) >> 5;
    if (w >= NN) return;
    int lane = threadIdx.x & 31;
    float ps[4] = {0, 0, 0, 0}, pd[4] = {0, 0, 0, 0};
    const float* xr = g_xs + (size_t)w * HC;
    #pragma unroll
    for (int j = 0; j < 8; j++) {
        int f = lane + 32 * j;           // head = j>>1 (f/64), lane-invariant
        float v = xr[f];
        ps[j >> 1] += v * atts[f];
        pd[j >> 1] += v * attd[f];
    }
    #pragma unroll
    for (int o = 16; o; o >>= 1) {
        #pragma unroll
        for (int h = 0; h < 4; h++) {
            ps[h] += __shfl_xor_sync(0xffffffffu, ps[h], o);
            pd[h] += __shfl_xor_sync(0xffffffffu, pd[h], o);
        }
    }
    if (lane == 0) {
        #pragma unroll
        for (int h = 0; h < 4; h++) {
            g_as[w * 4 + h] = ps[h];
            g_ad[w * 4 + h] = pd[h];
        }
    }
}

// ---------------- GAT aggregation (warp per dst node, gather formulation) ----------------
__global__ void k_agg(int layer, const float* __restrict__ bias) {
    int w = (blockIdx.x * blockDim.x + threadIdx.x) >> 5;
    if (w >= NN) return;
    int lane = threadIdx.x & 31;
    const float* ae = layer ? g_ae2 : g_ae1;
    int beg = g_offs[w], end = g_offs[w + 1];
    int deg = end - beg;
    float ad0 = g_ad[w * 4 + 0], ad1 = g_ad[w * 4 + 1];
    float ad2 = g_ad[w * 4 + 2], ad3 = g_ad[w * 4 + 3];

    // pass 1: max logits + sum of a_e (for mean self-loop attr)
    float m0 = -1e30f, m1 = -1e30f, m2 = -1e30f, m3 = -1e30f;
    float sa0 = 0, sa1 = 0, sa2 = 0, sa3 = 0;
    for (int i = beg + lane; i < end; i += 32) {
        int s = g_csrc[i], e = g_ceid[i];
        float4 aev = *(const float4*)(ae + (size_t)e * 4);
        float4 asv = *(const float4*)(g_as + (size_t)s * 4);
        sa0 += aev.x; sa1 += aev.y; sa2 += aev.z; sa3 += aev.w;
        m0 = fmaxf(m0, lrelu(asv.x + ad0 + aev.x));
        m1 = fmaxf(m1, lrelu(asv.y + ad1 + aev.y));
        m2 = fmaxf(m2, lrelu(asv.z + ad2 + aev.z));
        m3 = fmaxf(m3, lrelu(asv.w + ad3 + aev.w));
    }
    #pragma unroll
    for (int o = 16; o; o >>= 1) {
        m0 = fmaxf(m0, __shfl_xor_sync(0xffffffffu, m0, o));
        m1 = fmaxf(m1, __shfl_xor_sync(0xffffffffu, m1, o));
        m2 = fmaxf(m2, __shfl_xor_sync(0xffffffffu, m2, o));
        m3 = fmaxf(m3, __shfl_xor_sync(0xffffffffu, m3, o));
        sa0 += __shfl_xor_sync(0xffffffffu, sa0, o);
        sa1 += __shfl_xor_sync(0xffffffffu, sa1, o);
        sa2 += __shfl_xor_sync(0xffffffffu, sa2, o);
        sa3 += __shfl_xor_sync(0xffffffffu, sa3, o);
    }
    float invd = 1.0f / fmaxf((float)deg, 1.0f);
    float4 asn = *(const float4*)(g_as + (size_t)w * 4);
    float sl0 = lrelu(asn.x + ad0 + sa0 * invd);
    float sl1 = lrelu(asn.y + ad1 + sa1 * invd);
    float sl2 = lrelu(asn.z + ad2 + sa2 * invd);
    float sl3 = lrelu(asn.w + ad3 + sa3 * invd);
    m0 = fmaxf(m0, sl0); m1 = fmaxf(m1, sl1);
    m2 = fmaxf(m2, sl2); m3 = fmaxf(m3, sl3);

    // pass 2: unnormalized accumulate (acc = sum p_e * xs[src]); divide by den at end
    float den0 = 0, den1 = 0, den2 = 0, den3 = 0;
    float acc[8] = {0, 0, 0, 0, 0, 0, 0, 0};
    for (int base = beg; base < end; base += 32) {
        int i = base + lane;
        float p0 = 0, p1 = 0, p2 = 0, p3 = 0;
        int s = 0;
        if (i < end) {
            s = g_csrc[i];
            int e = g_ceid[i];
            float4 aev = *(const float4*)(ae + (size_t)e * 4);
            float4 asv = *(const float4*)(g_as + (size_t)s * 4);
            p0 = __expf(lrelu(asv.x + ad0 + aev.x) - m0);
            p1 = __expf(lrelu(asv.y + ad1 + aev.y) - m1);
            p2 = __expf(lrelu(asv.z + ad2 + aev.z) - m2);
            p3 = __expf(lrelu(asv.w + ad3 + aev.w) - m3);
            den0 += p0; den1 += p1; den2 += p2; den3 += p3;
        }
        int cnt = min(32, end - base);
        for (int jj = 0; jj < cnt; jj++) {
            int ss = __shfl_sync(0xffffffffu, s, jj);
            float q0 = __shfl_sync(0xffffffffu, p0, jj);
            float q1 = __shfl_sync(0xffffffffu, p1, jj);
            float q2 = __shfl_sync(0xffffffffu, p2, jj);
            float q3 = __shfl_sync(0xffffffffu, p3, jj);
            const float* xr = g_xs + (size_t)ss * HC + lane;
            acc[0] += q0 * xr[0];   acc[1] += q0 * xr[32];
            acc[2] += q1 * xr[64];  acc[3] += q1 * xr[96];
            acc[4] += q2 * xr[128]; acc[5] += q2 * xr[160];
            acc[6] += q3 * xr[192]; acc[7] += q3 * xr[224];
        }
    }
    #pragma unroll
    for (int o = 16; o; o >>= 1) {
        den0 += __shfl_xor_sync(0xffffffffu, den0, o);
        den1 += __shfl_xor_sync(0xffffffffu, den1, o);
        den2 += __shfl_xor_sync(0xffffffffu, den2, o);
        den3 += __shfl_xor_sync(0xffffffffu, den3, o);
    }
    float ps0 = __expf(sl0 - m0), ps1 = __expf(sl1 - m1);
    float ps2 = __expf(sl2 - m2), ps3 = __expf(sl3 - m3);
    den0 += ps0 + 1e-16f; den1 += ps1 + 1e-16f;
    den2 += ps2 + 1e-16f; den3 += ps3 + 1e-16f;
    const float* xn = g_xs + (size_t)w * HC + lane;
    acc[0] += ps0 * xn[0];   acc[1] += ps0 * xn[32];
    acc[2] += ps1 * xn[64];  acc[3] += ps1 * xn[96];
    acc[4] += ps2 * xn[128]; acc[5] += ps2 * xn[160];
    acc[6] += ps3 * xn[192]; acc[7] += ps3 * xn[224];
    float r0 = 1.f / den0, r1 = 1.f / den1, r2 = 1.f / den2, r3 = 1.f / den3;
    float* op = g_hpre + (size_t)w * HC + lane;
    const float* bp = bias + lane;
    op[0]   = acc[0] * r0 + bp[0];   op[32]  = acc[1] * r0 + bp[32];
    op[64]  = acc[2] * r1 + bp[64];  op[96]  = acc[3] * r1 + bp[96];
    op[128] = acc[4] * r2 + bp[128]; op[160] = acc[5] * r2 + bp[160];
    op[192] = acc[6] * r3 + bp[192]; op[224] = acc[7] * r3 + bp[224];
}

// ---------------- BN batch stats (sum, sumsq per column) ----------------
__global__ void k_stats(int off) {
    int c = threadIdx.x;    // 256
    int rows = (NN + gridDim.x - 1) / gridDim.x;
    int r0 = blockIdx.x * rows, r1 = min(r0 + rows, NN);
    float s = 0.f, s2 = 0.f;
    for (int r = r0; r < r1; r++) {
        float v = g_hpre[(size_t)r * HC + c];
        s += v;
        s2 = fmaf(v, v, s2);
    }
    atomicAdd(&g_stats[off + c], s);
    atomicAdd(&g_stats[off + 256 + c], s2);
}

__global__ void k_bnapply(const float* __restrict__ g, const float* __restrict__ be) {
    const float invN = 1.0f / NN;
    for (int i = blockIdx.x * blockDim.x + threadIdx.x; i < NN * HC;
         i += gridDim.x * blockDim.x) {
        int c = i & 255;
        float mu = g_stats[c] * invN;
        float var = g_stats[256 + c] * invN - mu * mu;
        float sc = g[c] * rsqrtf(var + 1e-5f);
        g_h1[i] = fmaxf(sc * (g_hpre[i] - mu) + be[c], 0.f);
    }
}

// ---------------- final: out[n] = relu(BN(hpre2)) . wout + bout ----------------
__global__ void k_final(const float* __restrict__ g, const float* __restrict__ be,
                        const float* __restrict__ wout, const float* __restrict__ bout,
                        float* __restrict__ out) {
    int w = (blockIdx.x * blockDim.x + threadIdx.x) >> 5;
    if (w >= NN) return;
    int lane = threadIdx.x & 31;
    const float invN = 1.0f / NN;
    float s = 0.f;
    #pragma unroll
    for (int j = 0; j < 8; j++) {
        int f = lane + 32 * j;
        float mu = g_stats[512 + f] * invN;
        float var = g_stats[768 + f] * invN - mu * mu;
        float sc = g[f] * rsqrtf(var + 1e-5f);
        float v = fmaxf(sc * (g_hpre[(size_t)w * HC + f] - mu) + be[f], 0.f);
        s += v * wout[f];
    }
    #pragma unroll
    for (int o = 16; o; o >>= 1) s += __shfl_xor_sync(0xffffffffu, s, o);
    if (lane == 0) out[w] = s + bout[0];
}

// ---------------- launch ----------------
extern "C" void kernel_launch(void* const* d_in, const int* in_sizes, int n_in,
                              void* d_out, int out_size) {
    const float* x     = (const float*)d_in[0];
    const int*   esrc  = (const int*)d_in[1];
    const int*   edst  = (const int*)d_in[2];
    const float* eattr = (const float*)d_in[3];
    const float* W1    = (const float*)d_in[4];
    const float* atts1 = (const float*)d_in[5];
    const float* attd1 = (const float*)d_in[6];
    const float* We1   = (const float*)d_in[7];
    const float* atte1 = (const float*)d_in[8];
    const float* b1    = (const float*)d_in[9];
    const float* g1    = (const float*)d_in[10];
    const float* be1   = (const float*)d_in[11];
    const float* W2    = (const float*)d_in[12];
    const float* atts2 = (const float*)d_in[13];
    const float* attd2 = (const float*)d_in[14];
    const float* We2   = (const float*)d_in[15];
    const float* atte2 = (const float*)d_in[16];
    const float* b2    = (const float*)d_in[17];
    const float* g2    = (const float*)d_in[18];
    const float* be2   = (const float*)d_in[19];
    const float* Wout  = (const float*)d_in[20];
    const float* bout  = (const float*)d_in[21];
    float* out = (float*)d_out;

    const int EB = (EE + 255) / 256;      // 3125
    const int NB = (NN + 255) / 256;      // 196 (scan blocks)
    const int WB = NN / 8;                // 6250 (warp-per-node kernels, 256 thr)
    dim3 gemmGrid(2, (NN + 127) / 128);   // 2 x 391

    // setup (edge-side, layer-independent)
    k_zero<<<NB, 256>>>();
    k_ve<<<1, 128>>>(We1, atte1, We2, atte2);
    k_edge<<<EB, 256>>>(eattr, edst);
    k_scan1<<<NB, 256>>>();
    k_scan2<<<1, 256>>>(NB);
    k_scan3<<<NB, 256>>>();
    k_fill<<<EB, 256>>>(esrc, edst);

    // layer 1
    k_sgemm<<<gemmGrid, 256>>>(x, W1, NN, 64);
    k_attdot<<<WB, 256>>>(atts1, attd1);
    k_agg<<<WB, 256>>>(0, b1);
    k_stats<<<256, 256>>>(0);
    k_bnapply<<<2048, 256>>>(g1, be1);

    // layer 2
    k_sgemm<<<gemmGrid, 256>>>(nullptr, W2, NN, 256);
    k_attdot<<<WB, 256>>>(atts2, attd2);
    k_agg<<<WB, 256>>>(1, b2);
    k_stats<<<256, 256>>>(512);

    // output head
    k_final<<<WB, 256>>>(g2, be2, Wout, bout, out);
}

// round 2
// speedup vs baseline: 1.0636x; 1.0636x over previous
#include <cuda_runtime.h>

#define NN 50000
#define EE 800000
#define HC 256

// ---------------- scratch (device globals; no allocation allowed) ----------------
__device__ float g_xs[NN * HC];     // xs of current layer (x@W)
__device__ float g_hpre[NN * HC];   // aggregated pre-BN output of current layer
__device__ float g_as[NN * 4];
__device__ float g_ad[NN * 4];
__device__ float g_ae1[EE * 4];     // edge order
__device__ float g_ae2[EE * 4];
__device__ float g_ae1c[EE * 4];    // CSR order
__device__ float g_ae2c[EE * 4];
__device__ int   g_deg[NN];
__device__ int   g_offs[NN + 1];
__device__ int   g_cursor[NN];
__device__ int   g_bsum[256];
__device__ int   g_bbase[257];
__device__ int   g_csrc[EE];
__device__ float g_ve1[64];         // [16,4]
__device__ float g_ve2[64];
__device__ float g_stats[1024];     // layer1: [0,512), layer2: [512,1024)
__device__ float g_bnsc[256];       // layer1 BN scale (fused into GEMM2 A-load)
__device__ float g_bnsh[256];       // layer1 BN shift

__device__ __forceinline__ float lrelu(float x) { return fmaxf(x, 0.2f * x); }

// ---------------- setup kernels ----------------
__global__ void k_zero() {
    int i = blockIdx.x * blockDim.x + threadIdx.x;
    if (i < NN) g_deg[i] = 0;
    if (i < 1024) g_stats[i] = 0.f;
}

// Ve[j][h] = sum_c We[j, h*64+c] * atte[h, c]   (collapses ee = ea2@We entirely)
__global__ void k_ve(const float* __restrict__ We1, const float* __restrict__ at1,
                     const float* __restrict__ We2, const float* __restrict__ at2) {
    int t = threadIdx.x;            // 128 threads
    int which = t >> 6;
    int u = t & 63;
    int j = u >> 2, h = u & 3;
    const float* We = which ? We2 : We1;
    const float* at = which ? at2 : at1;
    float s = 0.f;
    #pragma unroll 8
    for (int c = 0; c < 64; c++) s += We[j * HC + h * 64 + c] * at[h * 64 + c];
    if (which) g_ve2[u] = s; else g_ve1[u] = s;
}

// per-edge a_e for both layers + degree histogram
__global__ void k_edge(const float* __restrict__ eattr, const int* __restrict__ dst) {
    int e = blockIdx.x * blockDim.x + threadIdx.x;
    if (e >= EE) return;
    const float4* p = (const float4*)(eattr + (size_t)e * 16);
    float4 a = p[0], b = p[1], c = p[2], d = p[3];
    float v[16] = {a.x,a.y,a.z,a.w, b.x,b.y,b.z,b.w, c.x,c.y,c.z,c.w, d.x,d.y,d.z,d.w};
    float o1[4] = {0,0,0,0}, o2[4] = {0,0,0,0};
    #pragma unroll
    for (int j = 0; j < 16; j++) {
        #pragma unroll
        for (int h = 0; h < 4; h++) {
            o1[h] += v[j] * g_ve1[j * 4 + h];
            o2[h] += v[j] * g_ve2[j * 4 + h];
        }
    }
    *(float4*)(g_ae1 + (size_t)e * 4) = make_float4(o1[0], o1[1], o1[2], o1[3]);
    *(float4*)(g_ae2 + (size_t)e * 4) = make_float4(o2[0], o2[1], o2[2], o2[3]);
    atomicAdd(&g_deg[dst[e]], 1);
}

// ------------- 3-kernel exclusive scan of deg -> offs, cursor -------------
__global__ void k_scan1() {
    __shared__ int sh[256];
    int b = blockIdx.x, t = threadIdx.x;
    int i = b * 256 + t;
    sh[t] = (i < NN) ? g_deg[i] : 0;
    __syncthreads();
    for (int o = 128; o; o >>= 1) { if (t < o) sh[t] += sh[t + o]; __syncthreads(); }
    if (t == 0) g_bsum[b] = sh[0];
}

__global__ void k_scan2(int nb) {
    __shared__ int sh[256];
    int t = threadIdx.x;
    sh[t] = (t < nb) ? g_bsum[t] : 0;
    __syncthreads();
    for (int o = 1; o < 256; o <<= 1) {
        int v = (t >= o) ? sh[t - o] : 0;
        __syncthreads();
        sh[t] += v;
        __syncthreads();
    }
    g_bbase[t + 1] = sh[t];
    if (t == 0) { g_bbase[0] = 0; g_offs[NN] = EE; }
}

__global__ void k_scan3() {
    __shared__ int sh[256];
    int b = blockIdx.x, t = threadIdx.x;
    int i = b * 256 + t;
    int d = (i < NN) ? g_deg[i] : 0;
    sh[t] = d;
    __syncthreads();
    for (int o = 1; o < 256; o <<= 1) {
        int v = (t >= o) ? sh[t - o] : 0;
        __syncthreads();
        sh[t] += v;
        __syncthreads();
    }
    if (i < NN) {
        int off = g_bbase[b] + sh[t] - d;
        g_offs[i] = off;
        g_cursor[i] = off;
    }
}

// fill CSR: src ids + a_e permuted to CSR order (removes ceid indirection in agg)
__global__ void k_fill(const int* __restrict__ src, const int* __restrict__ dst) {
    int e = blockIdx.x * blockDim.x + threadIdx.x;
    if (e >= EE) return;
    int pos = atomicAdd(&g_cursor[dst[e]], 1);
    g_csrc[pos] = src[e];
    ((float4*)g_ae1c)[pos] = ((const float4*)g_ae1)[e];
    ((float4*)g_ae2c)[pos] = ((const float4*)g_ae2)[e];
}

// ---------------- SGEMM: C[M,256] = A[M,K] @ B[K,256], double-buffered,
// fused: optional BN-ReLU on A-load (layer2), attdot epilogue (a_s, a_d) --------
__global__ void __launch_bounds__(256)
k_sgemm(const float* __restrict__ Aext, const float* __restrict__ B, int M, int K,
        int bnflag, const float* __restrict__ atts, const float* __restrict__ attd) {
    const float* A = Aext ? Aext : g_hpre;
    __shared__ float As[2][8 * 132];
    __shared__ float Bs[2][8 * 128];
    int tid = threadIdx.x;
    int tx = tid & 15, ty = tid >> 4;
    int rowBlk = blockIdx.y * 128, colBlk = blockIdx.x * 128;
    int aRow = tid >> 1;
    int aCol = (tid & 1) * 4;
    int bRow = tid >> 5;
    int bCol = (tid & 31) * 4;
    bool aValid = (rowBlk + aRow) < M;
    const float* Ap = A + (size_t)(rowBlk + aRow) * K + aCol;
    const float* Bp = B + (size_t)bRow * 256 + colBlk + bCol;
    float acc[8][8];
    #pragma unroll
    for (int i = 0; i < 8; i++)
        #pragma unroll
        for (int j = 0; j < 8; j++) acc[i][j] = 0.f;

    // prologue: load k0=0 tile
    float4 av = aValid ? *(const float4*)(Ap) : make_float4(0, 0, 0, 0);
    if (bnflag && aValid) {
        float4 sc = *(const float4*)(g_bnsc + aCol);
        float4 sh = *(const float4*)(g_bnsh + aCol);
        av.x = fmaxf(fmaf(sc.x, av.x, sh.x), 0.f);
        av.y = fmaxf(fmaf(sc.y, av.y, sh.y), 0.f);
        av.z = fmaxf(fmaf(sc.z, av.z, sh.z), 0.f);
        av.w = fmaxf(fmaf(sc.w, av.w, sh.w), 0.f);
    }
    float4 bv = *(const float4*)(Bp);
    As[0][(aCol + 0) * 132 + aRow] = av.x;
    As[0][(aCol + 1) * 132 + aRow] = av.y;
    As[0][(aCol + 2) * 132 + aRow] = av.z;
    As[0][(aCol + 3) * 132 + aRow] = av.w;
    *(float4*)(&Bs[0][bRow * 128 + bCol]) = bv;
    __syncthreads();

    int cur = 0;
    for (int k0 = 0; k0 < K; k0 += 8) {
        int nxt = k0 + 8;
        float4 av2, bv2;
        if (nxt < K) {
            av2 = aValid ? *(const float4*)(Ap + nxt) : make_float4(0, 0, 0, 0);
            if (bnflag && aValid) {
                float4 sc = *(const float4*)(g_bnsc + nxt + aCol);
                float4 sh = *(const float4*)(g_bnsh + nxt + aCol);
                av2.x = fmaxf(fmaf(sc.x, av2.x, sh.x), 0.f);
                av2.y = fmaxf(fmaf(sc.y, av2.y, sh.y), 0.f);
                av2.z = fmaxf(fmaf(sc.z, av2.z, sh.z), 0.f);
                av2.w = fmaxf(fmaf(sc.w, av2.w, sh.w), 0.f);
            }
            bv2 = *(const float4*)(Bp + (size_t)nxt * 256);
        }
        #pragma unroll
        for (int k = 0; k < 8; k++) {
            float ra[8], rb[8];
            *(float4*)(ra)     = *(const float4*)(&As[cur][k * 132 + ty * 8]);
            *(float4*)(ra + 4) = *(const float4*)(&As[cur][k * 132 + ty * 8 + 4]);
            *(float4*)(rb)     = *(const float4*)(&Bs[cur][k * 128 + tx * 8]);
            *(float4*)(rb + 4) = *(const float4*)(&Bs[cur][k * 128 + tx * 8 + 4]);
            #pragma unroll
            for (int i = 0; i < 8; i++)
                #pragma unroll
                for (int j = 0; j < 8; j++)
                    acc[i][j] = fmaf(ra[i], rb[j], acc[i][j]);
        }
        if (nxt < K) {
            int nb = cur ^ 1;
            As[nb][(aCol + 0) * 132 + aRow] = av2.x;
            As[nb][(aCol + 1) * 132 + aRow] = av2.y;
            As[nb][(aCol + 2) * 132 + aRow] = av2.z;
            As[nb][(aCol + 3) * 132 + aRow] = av2.w;
            *(float4*)(&Bs[nb][bRow * 128 + bCol]) = bv2;
        }
        __syncthreads();
        cur ^= 1;
    }

    // epilogue: write C
    #pragma unroll
    for (int i = 0; i < 8; i++) {
        int r = rowBlk + ty * 8 + i;
        if (r < M) {
            float* Cp = g_xs + (size_t)r * 256 + colBlk + tx * 8;
            *(float4*)(Cp)     = make_float4(acc[i][0], acc[i][1], acc[i][2], acc[i][3]);
            *(float4*)(Cp + 4) = make_float4(acc[i][4], acc[i][5], acc[i][6], acc[i][7]);
        }
    }
    // fused attdot: per-head dots a_s, a_d (CTA's 128 cols = exactly 2 heads)
    int col0 = colBlk + tx * 8;
    float sv[8], dv[8];
    #pragma unroll
    for (int j = 0; j < 8; j++) { sv[j] = atts[col0 + j]; dv[j] = attd[col0 + j]; }
    int head = (colBlk >> 6) + ((tx >> 3) & 1);
    #pragma unroll
    for (int i = 0; i < 8; i++) {
        float ss = 0.f, dd = 0.f;
        #pragma unroll
        for (int j = 0; j < 8; j++) {
            ss = fmaf(acc[i][j], sv[j], ss);
            dd = fmaf(acc[i][j], dv[j], dd);
        }
        #pragma unroll
        for (int o = 4; o; o >>= 1) {
            ss += __shfl_xor_sync(0xffffffffu, ss, o);
            dd += __shfl_xor_sync(0xffffffffu, dd, o);
        }
        if ((tid & 7) == 0) {
            int r = rowBlk + ty * 8 + i;
            if (r < M) {
                g_as[r * 4 + head] = ss;
                g_ad[r * 4 + head] = dd;
            }
        }
    }
}

// ---------------- GAT aggregation: single pass (softmax shift-invariant, m=0),
// warp per dst node, lane owns 8 contiguous features (2x LDG.128 per edge) ------
__global__ void __launch_bounds__(256) k_agg(int layer, const float* __restrict__ bias) {
    int w = (blockIdx.x * blockDim.x + threadIdx.x) >> 5;
    if (w >= NN) return;
    int lane = threadIdx.x & 31;
    const float4* aeC = (const float4*)(layer ? g_ae2c : g_ae1c);
    int beg = g_offs[w], end = g_offs[w + 1];
    float4 adv = *(const float4*)(g_ad + (size_t)w * 4);
    int h = lane >> 3;
    int f0 = lane * 8;
    float acc[8] = {0, 0, 0, 0, 0, 0, 0, 0};
    float den0 = 0, den1 = 0, den2 = 0, den3 = 0;
    float sa0 = 0, sa1 = 0, sa2 = 0, sa3 = 0;

    for (int base = beg; base < end; base += 32) {
        int i = base + lane;
        float p0 = 0, p1 = 0, p2 = 0, p3 = 0;
        int s = 0;
        if (i < end) {
            s = g_csrc[i];
            float4 ae = aeC[i];
            float4 as = *(const float4*)(g_as + (size_t)s * 4);
            sa0 += ae.x; sa1 += ae.y; sa2 += ae.z; sa3 += ae.w;
            p0 = __expf(lrelu(as.x + adv.x + ae.x));
            p1 = __expf(lrelu(as.y + adv.y + ae.y));
            p2 = __expf(lrelu(as.z + adv.z + ae.z));
            p3 = __expf(lrelu(as.w + adv.w + ae.w));
            den0 += p0; den1 += p1; den2 += p2; den3 += p3;
        }
        int cnt = min(32, end - base);
        #pragma unroll 4
        for (int jj = 0; jj < cnt; jj++) {
            int ss = __shfl_sync(0xffffffffu, s, jj);
            float q0 = __shfl_sync(0xffffffffu, p0, jj);
            float q1 = __shfl_sync(0xffffffffu, p1, jj);
            float q2 = __shfl_sync(0xffffffffu, p2, jj);
            float q3 = __shfl_sync(0xffffffffu, p3, jj);
            float q = (h == 0) ? q0 : (h == 1) ? q1 : (h == 2) ? q2 : q3;
            const float4* xr = (const float4*)(g_xs + (size_t)ss * HC + f0);
            float4 xa = xr[0], xb = xr[1];
            acc[0] = fmaf(q, xa.x, acc[0]); acc[1] = fmaf(q, xa.y, acc[1]);
            acc[2] = fmaf(q, xa.z, acc[2]); acc[3] = fmaf(q, xa.w, acc[3]);
            acc[4] = fmaf(q, xb.x, acc[4]); acc[5] = fmaf(q, xb.y, acc[5]);
            acc[6] = fmaf(q, xb.z, acc[6]); acc[7] = fmaf(q, xb.w, acc[7]);
        }
    }
    #pragma unroll
    for (int o = 16; o; o >>= 1) {
        den0 += __shfl_xor_sync(0xffffffffu, den0, o);
        den1 += __shfl_xor_sync(0xffffffffu, den1, o);
        den2 += __shfl_xor_sync(0xffffffffu, den2, o);
        den3 += __shfl_xor_sync(0xffffffffu, den3, o);
        sa0 += __shfl_xor_sync(0xffffffffu, sa0, o);
        sa1 += __shfl_xor_sync(0xffffffffu, sa1, o);
        sa2 += __shfl_xor_sync(0xffffffffu, sa2, o);
        sa3 += __shfl_xor_sync(0xffffffffu, sa3, o);
    }
    int deg = end - beg;
    float invd = 1.0f / fmaxf((float)deg, 1.0f);
    float4 asn = *(const float4*)(g_as + (size_t)w * 4);
    float ps0 = __expf(lrelu(asn.x + adv.x + sa0 * invd));
    float ps1 = __expf(lrelu(asn.y + adv.y + sa1 * invd));
    float ps2 = __expf(lrelu(asn.z + adv.z + sa2 * invd));
    float ps3 = __expf(lrelu(asn.w + adv.w + sa3 * invd));
    den0 += ps0 + 1e-16f; den1 += ps1 + 1e-16f;
    den2 += ps2 + 1e-16f; den3 += ps3 + 1e-16f;
    const float4* xn = (const float4*)(g_xs + (size_t)w * HC + f0);
    float4 xa = xn[0], xb = xn[1];
    float psh = (h == 0) ? ps0 : (h == 1) ? ps1 : (h == 2) ? ps2 : ps3;
    acc[0] = fmaf(psh, xa.x, acc[0]); acc[1] = fmaf(psh, xa.y, acc[1]);
    acc[2] = fmaf(psh, xa.z, acc[2]); acc[3] = fmaf(psh, xa.w, acc[3]);
    acc[4] = fmaf(psh, xb.x, acc[4]); acc[5] = fmaf(psh, xb.y, acc[5]);
    acc[6] = fmaf(psh, xb.z, acc[6]); acc[7] = fmaf(psh, xb.w, acc[7]);
    float denh = (h == 0) ? den0 : (h == 1) ? den1 : (h == 2) ? den2 : den3;
    float r = 1.0f / denh;
    float4 b0 = *(const float4*)(bias + f0);
    float4 b1 = *(const float4*)(bias + f0 + 4);
    float* op = g_hpre + (size_t)w * HC + f0;
    *(float4*)(op)     = make_float4(fmaf(acc[0], r, b0.x), fmaf(acc[1], r, b0.y),
                                     fmaf(acc[2], r, b0.z), fmaf(acc[3], r, b0.w));
    *(float4*)(op + 4) = make_float4(fmaf(acc[4], r, b1.x), fmaf(acc[5], r, b1.y),
                                     fmaf(acc[6], r, b1.z), fmaf(acc[7], r, b1.w));
}

// ---------------- BN batch stats (sum, sumsq per column) ----------------
__global__ void k_stats(int off) {
    int c = threadIdx.x;    // 256
    int rows = (NN + gridDim.x - 1) / gridDim.x;
    int r0 = blockIdx.x * rows, r1 = min(r0 + rows, NN);
    float s = 0.f, s2 = 0.f;
    for (int r = r0; r < r1; r++) {
        float v = g_hpre[(size_t)r * HC + c];
        s += v;
        s2 = fmaf(v, v, s2);
    }
    atomicAdd(&g_stats[off + c], s);
    atomicAdd(&g_stats[off + 256 + c], s2);
}

// layer1 BN -> per-column scale/shift (consumed by GEMM2 A-load)
__global__ void k_bnprep(const float* __restrict__ g, const float* __restrict__ be) {
    int c = threadIdx.x;
    const float invN = 1.0f / NN;
    float mu = g_stats[c] * invN;
    float var = g_stats[256 + c] * invN - mu * mu;
    float sc = g[c] * rsqrtf(var + 1e-5f);
    g_bnsc[c] = sc;
    g_bnsh[c] = be[c] - sc * mu;
}

// ---------------- final: out[n] = relu(BN(hpre2)) . wout + bout ----------------
__global__ void k_final(const float* __restrict__ g, const float* __restrict__ be,
                        const float* __restrict__ wout, const float* __restrict__ bout,
                        float* __restrict__ out) {
    int w = (blockIdx.x * blockDim.x + threadIdx.x) >> 5;
    if (w >= NN) return;
    int lane = threadIdx.x & 31;
    const float invN = 1.0f / NN;
    float s = 0.f;
    #pragma unroll
    for (int j = 0; j < 8; j++) {
        int f = lane + 32 * j;
        float mu = g_stats[512 + f] * invN;
        float var = g_stats[768 + f] * invN - mu * mu;
        float sc = g[f] * rsqrtf(var + 1e-5f);
        float v = fmaxf(sc * (g_hpre[(size_t)w * HC + f] - mu) + be[f], 0.f);
        s = fmaf(v, wout[f], s);
    }
    #pragma unroll
    for (int o = 16; o; o >>= 1) s += __shfl_xor_sync(0xffffffffu, s, o);
    if (lane == 0) out[w] = s + bout[0];
}

// ---------------- launch ----------------
extern "C" void kernel_launch(void* const* d_in, const int* in_sizes, int n_in,
                              void* d_out, int out_size) {
    const float* x     = (const float*)d_in[0];
    const int*   esrc  = (const int*)d_in[1];
    const int*   edst  = (const int*)d_in[2];
    const float* eattr = (const float*)d_in[3];
    const float* W1    = (const float*)d_in[4];
    const float* atts1 = (const float*)d_in[5];
    const float* attd1 = (const float*)d_in[6];
    const float* We1   = (const float*)d_in[7];
    const float* atte1 = (const float*)d_in[8];
    const float* b1    = (const float*)d_in[9];
    const float* g1    = (const float*)d_in[10];
    const float* be1   = (const float*)d_in[11];
    const float* W2    = (const float*)d_in[12];
    const float* atts2 = (const float*)d_in[13];
    const float* attd2 = (const float*)d_in[14];
    const float* We2   = (const float*)d_in[15];
    const float* atte2 = (const float*)d_in[16];
    const float* b2    = (const float*)d_in[17];
    const float* g2    = (const float*)d_in[18];
    const float* be2   = (const float*)d_in[19];
    const float* Wout  = (const float*)d_in[20];
    const float* bout  = (const float*)d_in[21];
    float* out = (float*)d_out;

    const int EB = (EE + 255) / 256;
    const int NB = (NN + 255) / 256;
    const int WB = NN / 8;                // 6250 warp-per-node blocks (256 thr)
    dim3 gemmGrid(2, (NN + 127) / 128);

    k_zero<<<NB, 256>>>();
    k_ve<<<1, 128>>>(We1, atte1, We2, atte2);
    k_edge<<<EB, 256>>>(eattr, edst);
    k_scan1<<<NB, 256>>>();
    k_scan2<<<1, 256>>>(NB);
    // launch #5 -> profiled by ncu: GEMM1 (independent of scans; stream-serial anyway)
    k_sgemm<<<gemmGrid, 256>>>(x, W1, NN, 64, 0, atts1, attd1);
    k_scan3<<<NB, 256>>>();
    k_fill<<<EB, 256>>>(esrc, edst);

    // layer 1
    k_agg<<<WB, 256>>>(0, b1);
    k_stats<<<256, 256>>>(0);
    k_bnprep<<<1, 256>>>(g1, be1);

    // layer 2 (BN-ReLU of layer1 fused into A-load)
    k_sgemm<<<gemmGrid, 256>>>(nullptr, W2, NN, 256, 1, atts2, attd2);
    k_agg<<<WB, 256>>>(1, b2);
    k_stats<<<256, 256>>>(512);

    // output head
    k_final<<<WB, 256>>>(g2, be2, Wout, bout, out);
}

// round 3
// speedup vs baseline: 1.2337x; 1.1599x over previous
#include <cuda_runtime.h>
#include <cuda_bf16.h>

#define NN 50000
#define EE 800000
#define HC 256

// ---------------- scratch (device globals; no allocation allowed) ----------------
__device__ float g_xs[NN * HC];     // xs of current layer (x@W)
__device__ float g_hpre[NN * HC];   // aggregated pre-BN output of current layer
__device__ float g_as[NN * 4];
__device__ float g_ad[NN * 4];
__device__ float g_ae1[EE * 4];     // edge order
__device__ float g_ae2[EE * 4];
__device__ float g_ae1c[EE * 4];    // CSR order
__device__ float g_ae2c[EE * 4];
__device__ int   g_deg[NN];
__device__ int   g_offs[NN + 1];
__device__ int   g_cursor[NN];
__device__ int   g_bsum[256];
__device__ int   g_bbase[257];
__device__ int   g_csrc[EE];
__device__ float g_ve1[64];         // [16,4]
__device__ float g_ve2[64];
__device__ float g_stats[1024];     // layer1: [0,512), layer2: [512,1024)
__device__ float g_bnsc[256];       // layer1 BN scale (fused into GEMM2 A-load)
__device__ float g_bnsh[256];       // layer1 BN shift
// W pre-transposed [n][k], bf16 hi/lo planes, per layer
__device__ __align__(16) unsigned short g_WtH[2][256 * 256];
__device__ __align__(16) unsigned short g_WtL[2][256 * 256];

__device__ __forceinline__ float lrelu(float x) { return fmaxf(x, 0.2f * x); }

__device__ __forceinline__ void split_pk(float x0, float x1, unsigned& h, unsigned& l) {
    __nv_bfloat16 h0 = __float2bfloat16_rn(x0), h1 = __float2bfloat16_rn(x1);
    float r0 = x0 - __bfloat162float(h0), r1 = x1 - __bfloat162float(h1);
    __nv_bfloat16 l0 = __float2bfloat16_rn(r0), l1 = __float2bfloat16_rn(r1);
    h = (unsigned)__bfloat16_as_ushort(h0) | ((unsigned)__bfloat16_as_ushort(h1) << 16);
    l = (unsigned)__bfloat16_as_ushort(l0) | ((unsigned)__bfloat16_as_ushort(l1) << 16);
}

#define MMA_BF16(C, A0, A1, A2, A3, B0, B1)                                      \
    asm volatile("mma.sync.aligned.m16n8k16.row.col.f32.bf16.bf16.f32 "          \
                 "{%0,%1,%2,%3}, {%4,%5,%6,%7}, {%8,%9}, {%0,%1,%2,%3};\n"       \
                 : "+f"((C)[0]), "+f"((C)[1]), "+f"((C)[2]), "+f"((C)[3])        \
                 : "r"(A0), "r"(A1), "r"(A2), "r"(A3), "r"(B0), "r"(B1))

// ---------------- setup kernels ----------------
__global__ void k_zero() {
    int i = blockIdx.x * blockDim.x + threadIdx.x;
    if (i < NN) g_deg[i] = 0;
    if (i < 1024) g_stats[i] = 0.f;
}

// Ve[j][h] = sum_c We[j, h*64+c] * atte[h, c]
__global__ void k_ve(const float* __restrict__ We1, const float* __restrict__ at1,
                     const float* __restrict__ We2, const float* __restrict__ at2) {
    int t = threadIdx.x;            // 128 threads
    int which = t >> 6;
    int u = t & 63;
    int j = u >> 2, h = u & 3;
    const float* We = which ? We2 : We1;
    const float* at = which ? at2 : at1;
    float s = 0.f;
    #pragma unroll 8
    for (int c = 0; c < 64; c++) s += We[j * HC + h * 64 + c] * at[h * 64 + c];
    if (which) g_ve2[u] = s; else g_ve1[u] = s;
}

// W[K,256] fp32 -> Wt[n][k] bf16 hi/lo planes
__global__ void k_prepW(const float* __restrict__ W, int K, int layer) {
    int n = blockIdx.x;
    int k = threadIdx.x;
    if (k >= K) return;
    float x = W[(size_t)k * 256 + n];
    __nv_bfloat16 h = __float2bfloat16_rn(x);
    float lo = x - __bfloat162float(h);
    __nv_bfloat16 l = __float2bfloat16_rn(lo);
    g_WtH[layer][n * K + k] = __bfloat16_as_ushort(h);
    g_WtL[layer][n * K + k] = __bfloat16_as_ushort(l);
}

// per-edge a_e for both layers + degree histogram
__global__ void k_edge(const float* __restrict__ eattr, const int* __restrict__ dst) {
    int e = blockIdx.x * blockDim.x + threadIdx.x;
    if (e >= EE) return;
    const float4* p = (const float4*)(eattr + (size_t)e * 16);
    float4 a = p[0], b = p[1], c = p[2], d = p[3];
    float v[16] = {a.x,a.y,a.z,a.w, b.x,b.y,b.z,b.w, c.x,c.y,c.z,c.w, d.x,d.y,d.z,d.w};
    float o1[4] = {0,0,0,0}, o2[4] = {0,0,0,0};
    #pragma unroll
    for (int j = 0; j < 16; j++) {
        #pragma unroll
        for (int h = 0; h < 4; h++) {
            o1[h] += v[j] * g_ve1[j * 4 + h];
            o2[h] += v[j] * g_ve2[j * 4 + h];
        }
    }
    *(float4*)(g_ae1 + (size_t)e * 4) = make_float4(o1[0], o1[1], o1[2], o1[3]);
    *(float4*)(g_ae2 + (size_t)e * 4) = make_float4(o2[0], o2[1], o2[2], o2[3]);
    atomicAdd(&g_deg[dst[e]], 1);
}

// ------------- 3-kernel exclusive scan of deg -> offs, cursor -------------
__global__ void k_scan1() {
    __shared__ int sh[256];
    int b = blockIdx.x, t = threadIdx.x;
    int i = b * 256 + t;
    sh[t] = (i < NN) ? g_deg[i] : 0;
    __syncthreads();
    for (int o = 128; o; o >>= 1) { if (t < o) sh[t] += sh[t + o]; __syncthreads(); }
    if (t == 0) g_bsum[b] = sh[0];
}

__global__ void k_scan2(int nb) {
    __shared__ int sh[256];
    int t = threadIdx.x;
    sh[t] = (t < nb) ? g_bsum[t] : 0;
    __syncthreads();
    for (int o = 1; o < 256; o <<= 1) {
        int v = (t >= o) ? sh[t - o] : 0;
        __syncthreads();
        sh[t] += v;
        __syncthreads();
    }
    g_bbase[t + 1] = sh[t];
    if (t == 0) { g_bbase[0] = 0; g_offs[NN] = EE; }
}

__global__ void k_scan3() {
    __shared__ int sh[256];
    int b = blockIdx.x, t = threadIdx.x;
    int i = b * 256 + t;
    int d = (i < NN) ? g_deg[i] : 0;
    sh[t] = d;
    __syncthreads();
    for (int o = 1; o < 256; o <<= 1) {
        int v = (t >= o) ? sh[t - o] : 0;
        __syncthreads();
        sh[t] += v;
        __syncthreads();
    }
    if (i < NN) {
        int off = g_bbase[b] + sh[t] - d;
        g_offs[i] = off;
        g_cursor[i] = off;
    }
}

// fill CSR: src ids + a_e permuted to CSR order
__global__ void k_fill(const int* __restrict__ src, const int* __restrict__ dst) {
    int e = blockIdx.x * blockDim.x + threadIdx.x;
    if (e >= EE) return;
    int pos = atomicAdd(&g_cursor[dst[e]], 1);
    g_csrc[pos] = src[e];
    ((float4*)g_ae1c)[pos] = ((const float4*)g_ae1)[e];
    ((float4*)g_ae2c)[pos] = ((const float4*)g_ae2)[e];
}

// ---------------- tensor-core GEMM: C[M,256] = A[M,K] @ W, bf16 3-term split ----
// BM=128 BN=128 BK=16, 8 warps (2m x 4n), warp tile 64x32, mma m16n8k16.
// smem: [row][12 words] (12-word stride => conflict-free frag LDS).
// Optional fused BN-ReLU on A-load (layer2). Writes C to g_xs.
__global__ void __launch_bounds__(256, 2)
k_gemm(const float* __restrict__ Aext, int M, int K, int layer, int bnflag) {
    const float* A = Aext ? Aext : g_hpre;
    __shared__ unsigned sAh[128 * 12], sAl[128 * 12];
    __shared__ unsigned sBh[128 * 12], sBl[128 * 12];
    int tid = threadIdx.x;
    int lane = tid & 31, wid = tid >> 5;
    int wm = (wid >> 2) * 64, wn = (wid & 3) * 32;
    int rowBlk = blockIdx.y * 128, colBlk = blockIdx.x * 128;

    // A loader: thread -> (row = tid>>1, kbase = (tid&1)*8), 8 consecutive k
    int ar = tid >> 1;
    int ak = (tid & 1) * 8;
    bool aval = (rowBlk + ar) < M;
    const float* Ap = A + (size_t)(rowBlk + ar) * K + ak;
    // B loader: thread -> (n = tid&127, sel = tid>>7 hi/lo), 16 bf16 per chunk
    int bn_ = tid & 127;
    int bsel = tid >> 7;
    const unsigned short* Bp =
        (bsel ? g_WtL[layer] : g_WtH[layer]) + (size_t)(colBlk + bn_) * K;

    float c[4][4][4];
    #pragma unroll
    for (int mt = 0; mt < 4; mt++)
        #pragma unroll
        for (int nt = 0; nt < 4; nt++)
            #pragma unroll
            for (int q = 0; q < 4; q++) c[mt][nt][q] = 0.f;

    int nch = K >> 4;
    float av[8];
    uint4 bq0, bq1;

    // prefetch chunk 0
    {
        float4 u = aval ? *(const float4*)(Ap) : make_float4(0, 0, 0, 0);
        float4 v = aval ? *(const float4*)(Ap + 4) : make_float4(0, 0, 0, 0);
        av[0]=u.x; av[1]=u.y; av[2]=u.z; av[3]=u.w;
        av[4]=v.x; av[5]=v.y; av[6]=v.z; av[7]=v.w;
        bq0 = ((const uint4*)(Bp))[0];
        bq1 = ((const uint4*)(Bp))[1];
    }

    for (int ch = 0; ch < nch; ch++) {
        // BN-ReLU fuse (layer2) applied to staged A values
        if (bnflag && aval) {
            int kk = ch * 16 + ak;
            #pragma unroll
            for (int j = 0; j < 8; j++)
                av[j] = fmaxf(fmaf(g_bnsc[kk + j], av[j], g_bnsh[kk + j]), 0.f);
        }
        // stage -> smem
        {
            unsigned h0, h1, h2, h3, l0, l1, l2, l3;
            split_pk(av[0], av[1], h0, l0);
            split_pk(av[2], av[3], h1, l1);
            split_pk(av[4], av[5], h2, l2);
            split_pk(av[6], av[7], h3, l3);
            int base = ar * 12 + (ak >> 1);
            *(uint4*)(sAh + base) = make_uint4(h0, h1, h2, h3);
            *(uint4*)(sAl + base) = make_uint4(l0, l1, l2, l3);
            unsigned* sB = bsel ? sBl : sBh;
            int bb = bn_ * 12;
            *(uint4*)(sB + bb) = bq0;
            *(uint4*)(sB + bb + 4) = bq1;
        }
        __syncthreads();
        // prefetch next chunk
        if (ch + 1 < nch) {
            const float* Ap2 = Ap + (ch + 1) * 16;
            float4 u = aval ? *(const float4*)(Ap2) : make_float4(0, 0, 0, 0);
            float4 v = aval ? *(const float4*)(Ap2 + 4) : make_float4(0, 0, 0, 0);
            av[0]=u.x; av[1]=u.y; av[2]=u.z; av[3]=u.w;
            av[4]=v.x; av[5]=v.y; av[6]=v.z; av[7]=v.w;
            const uint4* Bc = (const uint4*)(Bp + (ch + 1) * 16);
            bq0 = Bc[0];
            bq1 = Bc[1];
        }
        // compute
        unsigned bh0[4], bh1[4], bl0[4], bl1[4];
        #pragma unroll
        for (int nt = 0; nt < 4; nt++) {
            int nb = (wn + nt * 8 + (lane >> 2)) * 12 + (lane & 3);
            bh0[nt] = sBh[nb]; bh1[nt] = sBh[nb + 4];
            bl0[nt] = sBl[nb]; bl1[nt] = sBl[nb + 4];
        }
        #pragma unroll
        for (int mt = 0; mt < 4; mt++) {
            int ab = (wm + mt * 16 + (lane >> 2)) * 12 + (lane & 3);
            unsigned ah0 = sAh[ab], ah1 = sAh[ab + 96];
            unsigned ah2 = sAh[ab + 4], ah3 = sAh[ab + 100];
            unsigned al0 = sAl[ab], al1 = sAl[ab + 96];
            unsigned al2 = sAl[ab + 4], al3 = sAl[ab + 100];
            #pragma unroll
            for (int nt = 0; nt < 4; nt++) {
                MMA_BF16(c[mt][nt], ah0, ah1, ah2, ah3, bh0[nt], bh1[nt]);
                MMA_BF16(c[mt][nt], ah0, ah1, ah2, ah3, bl0[nt], bl1[nt]);
                MMA_BF16(c[mt][nt], al0, al1, al2, al3, bh0[nt], bh1[nt]);
            }
        }
        __syncthreads();
    }

    // epilogue: c frag rows lane>>2 (+8), cols 2*(lane&3)(+1)
    #pragma unroll
    for (int mt = 0; mt < 4; mt++) {
        int r0 = rowBlk + wm + mt * 16 + (lane >> 2);
        #pragma unroll
        for (int nt = 0; nt < 4; nt++) {
            int col = colBlk + wn + nt * 8 + (lane & 3) * 2;
            if (r0 < M)
                *(float2*)(g_xs + (size_t)r0 * 256 + col) =
                    make_float2(c[mt][nt][0], c[mt][nt][1]);
            if (r0 + 8 < M)
                *(float2*)(g_xs + (size_t)(r0 + 8) * 256 + col) =
                    make_float2(c[mt][nt][2], c[mt][nt][3]);
        }
    }
}

// ---------------- per-node attention dots a_s, a_d (warp per node) ----------------
__global__ void k_attdot(const float* __restrict__ atts, const float* __restrict__ attd) {
    int w = (blockIdx.x * blockDim.x + threadIdx.x) >> 5;
    if (w >= NN) return;
    int lane = threadIdx.x & 31;
    float ps[4] = {0, 0, 0, 0}, pd[4] = {0, 0, 0, 0};
    const float* xr = g_xs + (size_t)w * HC;
    #pragma unroll
    for (int j = 0; j < 8; j++) {
        int f = lane + 32 * j;
        float v = xr[f];
        ps[j >> 1] += v * atts[f];
        pd[j >> 1] += v * attd[f];
    }
    #pragma unroll
    for (int o = 16; o; o >>= 1) {
        #pragma unroll
        for (int h = 0; h < 4; h++) {
            ps[h] += __shfl_xor_sync(0xffffffffu, ps[h], o);
            pd[h] += __shfl_xor_sync(0xffffffffu, pd[h], o);
        }
    }
    if (lane == 0) {
        #pragma unroll
        for (int h = 0; h < 4; h++) {
            g_as[w * 4 + h] = ps[h];
            g_ad[w * 4 + h] = pd[h];
        }
    }
}

// ---------------- GAT aggregation: single pass, warp per dst node ----------------
__global__ void __launch_bounds__(256) k_agg(int layer, const float* __restrict__ bias) {
    int w = (blockIdx.x * blockDim.x + threadIdx.x) >> 5;
    if (w >= NN) return;
    int lane = threadIdx.x & 31;
    const float4* aeC = (const float4*)(layer ? g_ae2c : g_ae1c);
    int beg = g_offs[w], end = g_offs[w + 1];
    float4 adv = *(const float4*)(g_ad + (size_t)w * 4);
    int h = lane >> 3;
    int f0 = lane * 8;
    float acc[8] = {0, 0, 0, 0, 0, 0, 0, 0};
    float den0 = 0, den1 = 0, den2 = 0, den3 = 0;
    float sa0 = 0, sa1 = 0, sa2 = 0, sa3 = 0;

    for (int base = beg; base < end; base += 32) {
        int i = base + lane;
        float p0 = 0, p1 = 0, p2 = 0, p3 = 0;
        int s = 0;
        if (i < end) {
            s = g_csrc[i];
            float4 ae = aeC[i];
            float4 as = *(const float4*)(g_as + (size_t)s * 4);
            sa0 += ae.x; sa1 += ae.y; sa2 += ae.z; sa3 += ae.w;
            p0 = __expf(lrelu(as.x + adv.x + ae.x));
            p1 = __expf(lrelu(as.y + adv.y + ae.y));
            p2 = __expf(lrelu(as.z + adv.z + ae.z));
            p3 = __expf(lrelu(as.w + adv.w + ae.w));
            den0 += p0; den1 += p1; den2 += p2; den3 += p3;
        }
        int cnt = min(32, end - base);
        #pragma unroll 4
        for (int jj = 0; jj < cnt; jj++) {
            int ss = __shfl_sync(0xffffffffu, s, jj);
            float q0 = __shfl_sync(0xffffffffu, p0, jj);
            float q1 = __shfl_sync(0xffffffffu, p1, jj);
            float q2 = __shfl_sync(0xffffffffu, p2, jj);
            float q3 = __shfl_sync(0xffffffffu, p3, jj);
            float q = (h == 0) ? q0 : (h == 1) ? q1 : (h == 2) ? q2 : q3;
            const float4* xr = (const float4*)(g_xs + (size_t)ss * HC + f0);
            float4 xa = xr[0], xb = xr[1];
            acc[0] = fmaf(q, xa.x, acc[0]); acc[1] = fmaf(q, xa.y, acc[1]);
            acc[2] = fmaf(q, xa.z, acc[2]); acc[3] = fmaf(q, xa.w, acc[3]);
            acc[4] = fmaf(q, xb.x, acc[4]); acc[5] = fmaf(q, xb.y, acc[5]);
            acc[6] = fmaf(q, xb.z, acc[6]); acc[7] = fmaf(q, xb.w, acc[7]);
        }
    }
    #pragma unroll
    for (int o = 16; o; o >>= 1) {
        den0 += __shfl_xor_sync(0xffffffffu, den0, o);
        den1 += __shfl_xor_sync(0xffffffffu, den1, o);
        den2 += __shfl_xor_sync(0xffffffffu, den2, o);
        den3 += __shfl_xor_sync(0xffffffffu, den3, o);
        sa0 += __shfl_xor_sync(0xffffffffu, sa0, o);
        sa1 += __shfl_xor_sync(0xffffffffu, sa1, o);
        sa2 += __shfl_xor_sync(0xffffffffu, sa2, o);
        sa3 += __shfl_xor_sync(0xffffffffu, sa3, o);
    }
    int deg = end - beg;
    float invd = 1.0f / fmaxf((float)deg, 1.0f);
    float4 asn = *(const float4*)(g_as + (size_t)w * 4);
    float ps0 = __expf(lrelu(asn.x + adv.x + sa0 * invd));
    float ps1 = __expf(lrelu(asn.y + adv.y + sa1 * invd));
    float ps2 = __expf(lrelu(asn.z + adv.z + sa2 * invd));
    float ps3 = __expf(lrelu(asn.w + adv.w + sa3 * invd));
    den0 += ps0 + 1e-16f; den1 += ps1 + 1e-16f;
    den2 += ps2 + 1e-16f; den3 += ps3 + 1e-16f;
    const float4* xn = (const float4*)(g_xs + (size_t)w * HC + f0);
    float4 xa = xn[0], xb = xn[1];
    float psh = (h == 0) ? ps0 : (h == 1) ? ps1 : (h == 2) ? ps2 : ps3;
    acc[0] = fmaf(psh, xa.x, acc[0]); acc[1] = fmaf(psh, xa.y, acc[1]);
    acc[2] = fmaf(psh, xa.z, acc[2]); acc[3] = fmaf(psh, xa.w, acc[3]);
    acc[4] = fmaf(psh, xb.x, acc[4]); acc[5] = fmaf(psh, xb.y, acc[5]);
    acc[6] = fmaf(psh, xb.z, acc[6]); acc[7] = fmaf(psh, xb.w, acc[7]);
    float denh = (h == 0) ? den0 : (h == 1) ? den1 : (h == 2) ? den2 : den3;
    float r = 1.0f / denh;
    float4 b0 = *(const float4*)(bias + f0);
    float4 b1 = *(const float4*)(bias + f0 + 4);
    float* op = g_hpre + (size_t)w * HC + f0;
    *(float4*)(op)     = make_float4(fmaf(acc[0], r, b0.x), fmaf(acc[1], r, b0.y),
                                     fmaf(acc[2], r, b0.z), fmaf(acc[3], r, b0.w));
    *(float4*)(op + 4) = make_float4(fmaf(acc[4], r, b1.x), fmaf(acc[5], r, b1.y),
                                     fmaf(acc[6], r, b1.z), fmaf(acc[7], r, b1.w));
}

// ---------------- BN batch stats (sum, sumsq per column) ----------------
__global__ void k_stats(int off) {
    int c = threadIdx.x;    // 256
    int rows = (NN + gridDim.x - 1) / gridDim.x;
    int r0 = blockIdx.x * rows, r1 = min(r0 + rows, NN);
    float s = 0.f, s2 = 0.f;
    for (int r = r0; r < r1; r++) {
        float v = g_hpre[(size_t)r * HC + c];
        s += v;
        s2 = fmaf(v, v, s2);
    }
    atomicAdd(&g_stats[off + c], s);
    atomicAdd(&g_stats[off + 256 + c], s2);
}

// layer1 BN -> per-column scale/shift (consumed by GEMM2 A-load)
__global__ void k_bnprep(const float* __restrict__ g, const float* __restrict__ be) {
    int c = threadIdx.x;
    const float invN = 1.0f / NN;
    float mu = g_stats[c] * invN;
    float var = g_stats[256 + c] * invN - mu * mu;
    float sc = g[c] * rsqrtf(var + 1e-5f);
    g_bnsc[c] = sc;
    g_bnsh[c] = be[c] - sc * mu;
}

// ---------------- final: out[n] = relu(BN(hpre2)) . wout + bout ----------------
__global__ void k_final(const float* __restrict__ g, const float* __restrict__ be,
                        const float* __restrict__ wout, const float* __restrict__ bout,
                        float* __restrict__ out) {
    int w = (blockIdx.x * blockDim.x + threadIdx.x) >> 5;
    if (w >= NN) return;
    int lane = threadIdx.x & 31;
    const float invN = 1.0f / NN;
    float s = 0.f;
    #pragma unroll
    for (int j = 0; j < 8; j++) {
        int f = lane + 32 * j;
        float mu = g_stats[512 + f] * invN;
        float var = g_stats[768 + f] * invN - mu * mu;
        float sc = g[f] * rsqrtf(var + 1e-5f);
        float v = fmaxf(sc * (g_hpre[(size_t)w * HC + f] - mu) + be[f], 0.f);
        s = fmaf(v, wout[f], s);
    }
    #pragma unroll
    for (int o = 16; o; o >>= 1) s += __shfl_xor_sync(0xffffffffu, s, o);
    if (lane == 0) out[w] = s + bout[0];
}

// ---------------- launch ----------------
extern "C" void kernel_launch(void* const* d_in, const int* in_sizes, int n_in,
                              void* d_out, int out_size) {
    const float* x     = (const float*)d_in[0];
    const int*   esrc  = (const int*)d_in[1];
    const int*   edst  = (const int*)d_in[2];
    const float* eattr = (const float*)d_in[3];
    const float* W1    = (const float*)d_in[4];
    const float* atts1 = (const float*)d_in[5];
    const float* attd1 = (const float*)d_in[6];
    const float* We1   = (const float*)d_in[7];
    const float* atte1 = (const float*)d_in[8];
    const float* b1    = (const float*)d_in[9];
    const float* g1    = (const float*)d_in[10];
    const float* be1   = (const float*)d_in[11];
    const float* W2    = (const float*)d_in[12];
    const float* atts2 = (const float*)d_in[13];
    const float* attd2 = (const float*)d_in[14];
    const float* We2   = (const float*)d_in[15];
    const float* atte2 = (const float*)d_in[16];
    const float* b2    = (const float*)d_in[17];
    const float* g2    = (const float*)d_in[18];
    const float* be2   = (const float*)d_in[19];
    const float* Wout  = (const float*)d_in[20];
    const float* bout  = (const float*)d_in[21];
    float* out = (float*)d_out;

    const int EB = (EE + 255) / 256;
    const int NB = (NN + 255) / 256;
    const int WB = NN / 8;                 // warp-per-node kernels (256 thr)
    dim3 gg(2, (NN + 127) / 128);

    // setup
    k_zero<<<NB, 256>>>();
    k_ve<<<1, 128>>>(We1, atte1, We2, atte2);
    k_prepW<<<256, 64>>>(W1, 64, 0);
    k_prepW<<<256, 256>>>(W2, 256, 1);
    k_edge<<<EB, 256>>>(eattr, edst);
    k_scan1<<<NB, 256>>>();
    k_scan2<<<1, 256>>>(NB);
    k_scan3<<<NB, 256>>>();
    k_fill<<<EB, 256>>>(esrc, edst);

    // layer 1
    k_gemm<<<gg, 256>>>(x, NN, 64, 0, 0);
    k_attdot<<<WB, 256>>>(atts1, attd1);
    k_agg<<<WB, 256>>>(0, b1);
    k_stats<<<256, 256>>>(0);
    k_bnprep<<<1, 256>>>(g1, be1);

    // layer 2 (BN-ReLU of layer1 fused into GEMM A-load)
    k_gemm<<<gg, 256>>>(nullptr, NN, 256, 1, 1);
    k_attdot<<<WB, 256>>>(atts2, attd2);
    k_agg<<<WB, 256>>>(1, b2);
    k_stats<<<256, 256>>>(512);

    // output head
    k_final<<<WB, 256>>>(g2, be2, Wout, bout, out);
}

// round 4
// speedup vs baseline: 1.3381x; 1.0846x over previous
#include <cuda_runtime.h>
#include <cuda_bf16.h>

#define NN 50000
#define EE 800000
#define HC 256

// ---------------- scratch (device globals; no allocation allowed) ----------------
__device__ float g_xs[NN * HC];     // xs of current layer (x@W)
__device__ float g_hpre[NN * HC];   // aggregated pre-BN output of current layer
__device__ float g_as[NN * 4];
__device__ float g_ad[NN * 4];
__device__ float g_ae1[EE * 4];     // edge order
__device__ float g_ae2[EE * 4];
__device__ float g_ae1c[EE * 4];    // CSR order
__device__ float g_ae2c[EE * 4];
__device__ int   g_deg[NN];
__device__ int   g_offs[NN + 1];
__device__ int   g_cursor[NN];
__device__ int   g_bsum[256];
__device__ int   g_bbase[257];
__device__ int   g_csrc[EE];
__device__ float g_ve1[64];         // [16,4]
__device__ float g_ve2[64];
__device__ float g_stats[1024];     // layer1: [0,512), layer2: [512,1024)
__device__ float g_bnsc[256];       // layer1 BN scale (fused into GEMM2 A-load)
__device__ float g_bnsh[256];       // layer1 BN shift
// W pre-transposed [n][k], bf16 hi/lo planes, per layer
__device__ __align__(16) unsigned short g_WtH[2][256 * 256];
__device__ __align__(16) unsigned short g_WtL[2][256 * 256];

__device__ __forceinline__ float lrelu(float x) { return fmaxf(x, 0.2f * x); }

__device__ __forceinline__ void split_pk(float x0, float x1, unsigned& h, unsigned& l) {
    __nv_bfloat16 h0 = __float2bfloat16_rn(x0), h1 = __float2bfloat16_rn(x1);
    float r0 = x0 - __bfloat162float(h0), r1 = x1 - __bfloat162float(h1);
    __nv_bfloat16 l0 = __float2bfloat16_rn(r0), l1 = __float2bfloat16_rn(r1);
    h = (unsigned)__bfloat16_as_ushort(h0) | ((unsigned)__bfloat16_as_ushort(h1) << 16);
    l = (unsigned)__bfloat16_as_ushort(l0) | ((unsigned)__bfloat16_as_ushort(l1) << 16);
}

#define MMA_BF16(C, A0, A1, A2, A3, B0, B1)                                      \
    asm volatile("mma.sync.aligned.m16n8k16.row.col.f32.bf16.bf16.f32 "          \
                 "{%0,%1,%2,%3}, {%4,%5,%6,%7}, {%8,%9}, {%0,%1,%2,%3};\n"       \
                 : "+f"((C)[0]), "+f"((C)[1]), "+f"((C)[2]), "+f"((C)[3])        \
                 : "r"(A0), "r"(A1), "r"(A2), "r"(A3), "r"(B0), "r"(B1))

// ---------------- setup kernels ----------------
__global__ void k_zero() {
    int i = blockIdx.x * blockDim.x + threadIdx.x;
    if (i < NN) g_deg[i] = 0;
    if (i < 1024) g_stats[i] = 0.f;
}

// Ve[j][h] = sum_c We[j, h*64+c] * atte[h, c]
__global__ void k_ve(const float* __restrict__ We1, const float* __restrict__ at1,
                     const float* __restrict__ We2, const float* __restrict__ at2) {
    int t = threadIdx.x;            // 128 threads
    int which = t >> 6;
    int u = t & 63;
    int j = u >> 2, h = u & 3;
    const float* We = which ? We2 : We1;
    const float* at = which ? at2 : at1;
    float s = 0.f;
    #pragma unroll 8
    for (int c = 0; c < 64; c++) s += We[j * HC + h * 64 + c] * at[h * 64 + c];
    if (which) g_ve2[u] = s; else g_ve1[u] = s;
}

// W[K,256] fp32 -> Wt[n][k] bf16 hi/lo planes
__global__ void k_prepW(const float* __restrict__ W, int K, int layer) {
    int n = blockIdx.x;
    int k = threadIdx.x;
    if (k >= K) return;
    float x = W[(size_t)k * 256 + n];
    __nv_bfloat16 h = __float2bfloat16_rn(x);
    float lo = x - __bfloat162float(h);
    __nv_bfloat16 l = __float2bfloat16_rn(lo);
    g_WtH[layer][n * K + k] = __bfloat16_as_ushort(h);
    g_WtL[layer][n * K + k] = __bfloat16_as_ushort(l);
}

// per-edge a_e for both layers + degree histogram
__global__ void k_edge(const float* __restrict__ eattr, const int* __restrict__ dst) {
    int e = blockIdx.x * blockDim.x + threadIdx.x;
    if (e >= EE) return;
    const float4* p = (const float4*)(eattr + (size_t)e * 16);
    float4 a = p[0], b = p[1], c = p[2], d = p[3];
    float v[16] = {a.x,a.y,a.z,a.w, b.x,b.y,b.z,b.w, c.x,c.y,c.z,c.w, d.x,d.y,d.z,d.w};
    float o1[4] = {0,0,0,0}, o2[4] = {0,0,0,0};
    #pragma unroll
    for (int j = 0; j < 16; j++) {
        #pragma unroll
        for (int h = 0; h < 4; h++) {
            o1[h] += v[j] * g_ve1[j * 4 + h];
            o2[h] += v[j] * g_ve2[j * 4 + h];
        }
    }
    *(float4*)(g_ae1 + (size_t)e * 4) = make_float4(o1[0], o1[1], o1[2], o1[3]);
    *(float4*)(g_ae2 + (size_t)e * 4) = make_float4(o2[0], o2[1], o2[2], o2[3]);
    atomicAdd(&g_deg[dst[e]], 1);
}

// ------------- 3-kernel exclusive scan of deg -> offs, cursor -------------
__global__ void k_scan1() {
    __shared__ int sh[256];
    int b = blockIdx.x, t = threadIdx.x;
    int i = b * 256 + t;
    sh[t] = (i < NN) ? g_deg[i] : 0;
    __syncthreads();
    for (int o = 128; o; o >>= 1) { if (t < o) sh[t] += sh[t + o]; __syncthreads(); }
    if (t == 0) g_bsum[b] = sh[0];
}

__global__ void k_scan2(int nb) {
    __shared__ int sh[256];
    int t = threadIdx.x;
    sh[t] = (t < nb) ? g_bsum[t] : 0;
    __syncthreads();
    for (int o = 1; o < 256; o <<= 1) {
        int v = (t >= o) ? sh[t - o] : 0;
        __syncthreads();
        sh[t] += v;
        __syncthreads();
    }
    g_bbase[t + 1] = sh[t];
    if (t == 0) { g_bbase[0] = 0; g_offs[NN] = EE; }
}

__global__ void k_scan3() {
    __shared__ int sh[256];
    int b = blockIdx.x, t = threadIdx.x;
    int i = b * 256 + t;
    int d = (i < NN) ? g_deg[i] : 0;
    sh[t] = d;
    __syncthreads();
    for (int o = 1; o < 256; o <<= 1) {
        int v = (t >= o) ? sh[t - o] : 0;
        __syncthreads();
        sh[t] += v;
        __syncthreads();
    }
    if (i < NN) {
        int off = g_bbase[b] + sh[t] - d;
        g_offs[i] = off;
        g_cursor[i] = off;
    }
}

// fill CSR: src ids + a_e permuted to CSR order
__global__ void k_fill(const int* __restrict__ src, const int* __restrict__ dst) {
    int e = blockIdx.x * blockDim.x + threadIdx.x;
    if (e >= EE) return;
    int pos = atomicAdd(&g_cursor[dst[e]], 1);
    g_csrc[pos] = src[e];
    ((float4*)g_ae1c)[pos] = ((const float4*)g_ae1)[e];
    ((float4*)g_ae2c)[pos] = ((const float4*)g_ae2)[e];
}

// ---------------- tensor-core GEMM: C[M,256] = A[M,K] @ W, bf16 3-term split ----
// BM=128 BN=128 BK=16, 8 warps (2m x 4n), warp tile 64x32, mma m16n8k16.
// Fused: optional BN-ReLU on A-load (layer2), attdot epilogue (a_s, a_d).
__global__ void __launch_bounds__(256, 2)
k_gemm(const float* __restrict__ Aext, int M, int K, int layer, int bnflag,
       const float* __restrict__ atts, const float* __restrict__ attd) {
    const float* A = Aext ? Aext : g_hpre;
    __shared__ unsigned sAh[128 * 12], sAl[128 * 12];
    __shared__ unsigned sBh[128 * 12], sBl[128 * 12];
    __shared__ float2 sred[4][128];
    int tid = threadIdx.x;
    int lane = tid & 31, wid = tid >> 5;
    int wm = (wid >> 2) * 64, wn = (wid & 3) * 32;
    int rowBlk = blockIdx.y * 128, colBlk = blockIdx.x * 128;

    int ar = tid >> 1;
    int ak = (tid & 1) * 8;
    bool aval = (rowBlk + ar) < M;
    const float* Ap = A + (size_t)(rowBlk + ar) * K + ak;
    int bn_ = tid & 127;
    int bsel = tid >> 7;
    const unsigned short* Bp =
        (bsel ? g_WtL[layer] : g_WtH[layer]) + (size_t)(colBlk + bn_) * K;

    float c[4][4][4];
    #pragma unroll
    for (int mt = 0; mt < 4; mt++)
        #pragma unroll
        for (int nt = 0; nt < 4; nt++)
            #pragma unroll
            for (int q = 0; q < 4; q++) c[mt][nt][q] = 0.f;

    int nch = K >> 4;
    float av[8];
    uint4 bq0, bq1;
    {
        float4 u = aval ? *(const float4*)(Ap) : make_float4(0, 0, 0, 0);
        float4 v = aval ? *(const float4*)(Ap + 4) : make_float4(0, 0, 0, 0);
        av[0]=u.x; av[1]=u.y; av[2]=u.z; av[3]=u.w;
        av[4]=v.x; av[5]=v.y; av[6]=v.z; av[7]=v.w;
        bq0 = ((const uint4*)(Bp))[0];
        bq1 = ((const uint4*)(Bp))[1];
    }

    for (int ch = 0; ch < nch; ch++) {
        if (bnflag && aval) {
            int kk = ch * 16 + ak;
            #pragma unroll
            for (int j = 0; j < 8; j++)
                av[j] = fmaxf(fmaf(g_bnsc[kk + j], av[j], g_bnsh[kk + j]), 0.f);
        }
        {
            unsigned h0, h1, h2, h3, l0, l1, l2, l3;
            split_pk(av[0], av[1], h0, l0);
            split_pk(av[2], av[3], h1, l1);
            split_pk(av[4], av[5], h2, l2);
            split_pk(av[6], av[7], h3, l3);
            int base = ar * 12 + (ak >> 1);
            *(uint4*)(sAh + base) = make_uint4(h0, h1, h2, h3);
            *(uint4*)(sAl + base) = make_uint4(l0, l1, l2, l3);
            unsigned* sB = bsel ? sBl : sBh;
            int bb = bn_ * 12;
            *(uint4*)(sB + bb) = bq0;
            *(uint4*)(sB + bb + 4) = bq1;
        }
        __syncthreads();
        if (ch + 1 < nch) {
            const float* Ap2 = Ap + (ch + 1) * 16;
            float4 u = aval ? *(const float4*)(Ap2) : make_float4(0, 0, 0, 0);
            float4 v = aval ? *(const float4*)(Ap2 + 4) : make_float4(0, 0, 0, 0);
            av[0]=u.x; av[1]=u.y; av[2]=u.z; av[3]=u.w;
            av[4]=v.x; av[5]=v.y; av[6]=v.z; av[7]=v.w;
            const uint4* Bc = (const uint4*)(Bp + (ch + 1) * 16);
            bq0 = Bc[0];
            bq1 = Bc[1];
        }
        unsigned bh0[4], bh1[4], bl0[4], bl1[4];
        #pragma unroll
        for (int nt = 0; nt < 4; nt++) {
            int nb = (wn + nt * 8 + (lane >> 2)) * 12 + (lane & 3);
            bh0[nt] = sBh[nb]; bh1[nt] = sBh[nb + 4];
            bl0[nt] = sBl[nb]; bl1[nt] = sBl[nb + 4];
        }
        #pragma unroll
        for (int mt = 0; mt < 4; mt++) {
            int ab = (wm + mt * 16 + (lane >> 2)) * 12 + (lane & 3);
            unsigned ah0 = sAh[ab], ah1 = sAh[ab + 96];
            unsigned ah2 = sAh[ab + 4], ah3 = sAh[ab + 100];
            unsigned al0 = sAl[ab], al1 = sAl[ab + 96];
            unsigned al2 = sAl[ab + 4], al3 = sAl[ab + 100];
            #pragma unroll
            for (int nt = 0; nt < 4; nt++) {
                MMA_BF16(c[mt][nt], ah0, ah1, ah2, ah3, bh0[nt], bh1[nt]);
                MMA_BF16(c[mt][nt], ah0, ah1, ah2, ah3, bl0[nt], bl1[nt]);
                MMA_BF16(c[mt][nt], al0, al1, al2, al3, bh0[nt], bh1[nt]);
            }
        }
        __syncthreads();
    }

    // epilogue: write C
    #pragma unroll
    for (int mt = 0; mt < 4; mt++) {
        int r0 = rowBlk + wm + mt * 16 + (lane >> 2);
        #pragma unroll
        for (int nt = 0; nt < 4; nt++) {
            int col = colBlk + wn + nt * 8 + (lane & 3) * 2;
            if (r0 < M)
                *(float2*)(g_xs + (size_t)r0 * 256 + col) =
                    make_float2(c[mt][nt][0], c[mt][nt][1]);
            if (r0 + 8 < M)
                *(float2*)(g_xs + (size_t)(r0 + 8) * 256 + col) =
                    make_float2(c[mt][nt][2], c[mt][nt][3]);
        }
    }
    // fused attdot: partial dots per n-warp -> smem -> reduce -> g_as/g_ad.
    // CTA covers cols [colBlk, colBlk+128) = heads {colBlk/64, colBlk/64+1}; the
    // two n-warp pairs {0,1},{2,3} each cover one full head. No cross-CTA overlap.
    float sv[4][2], dv[4][2];
    #pragma unroll
    for (int nt = 0; nt < 4; nt++)
        #pragma unroll
        for (int q = 0; q < 2; q++) {
            int col = colBlk + wn + nt * 8 + (lane & 3) * 2 + q;
            sv[nt][q] = atts[col];
            dv[nt][q] = attd[col];
        }
    #pragma unroll
    for (int mt = 0; mt < 4; mt++) {
        #pragma unroll
        for (int half = 0; half < 2; half++) {
            float ss = 0.f, dd = 0.f;
            #pragma unroll
            for (int nt = 0; nt < 4; nt++) {
                #pragma unroll
                for (int q = 0; q < 2; q++) {
                    ss = fmaf(c[mt][nt][half * 2 + q], sv[nt][q], ss);
                    dd = fmaf(c[mt][nt][half * 2 + q], dv[nt][q], dd);
                }
            }
            ss += __shfl_xor_sync(0xffffffffu, ss, 1);
            ss += __shfl_xor_sync(0xffffffffu, ss, 2);
            dd += __shfl_xor_sync(0xffffffffu, dd, 1);
            dd += __shfl_xor_sync(0xffffffffu, dd, 2);
            if ((lane & 3) == 0)
                sred[wid & 3][wm + mt * 16 + half * 8 + (lane >> 2)] =
                    make_float2(ss, dd);
        }
    }
    __syncthreads();
    {
        int row = tid >> 1, hl = tid & 1;
        int r = rowBlk + row;
        if (r < M) {
            float2 aa = sred[2 * hl][row], bb = sred[2 * hl + 1][row];
            int hidx = (colBlk >> 6) + hl;
            g_as[r * 4 + hidx] = aa.x + bb.x;
            g_ad[r * 4 + hidx] = aa.y + bb.y;
        }
    }
}

// ---------------- GAT aggregation: single pass, warp per dst node.
// smem staging of (src, p) replaces the 5-SHFL broadcast chain per edge. --------
__global__ void __launch_bounds__(256) k_agg(int layer, const float* __restrict__ bias) {
    __shared__ float4 sp[8][32];
    __shared__ int    si[8][32];
    int w = (blockIdx.x * blockDim.x + threadIdx.x) >> 5;
    if (w >= NN) return;
    int lane = threadIdx.x & 31;
    int wrp = threadIdx.x >> 5;
    const float4* aeC = (const float4*)(layer ? g_ae2c : g_ae1c);
    int beg = g_offs[w], end = g_offs[w + 1];
    float4 adv = *(const float4*)(g_ad + (size_t)w * 4);
    int h = lane >> 3;
    int f0 = lane * 8;
    float acc[8] = {0, 0, 0, 0, 0, 0, 0, 0};
    float den0 = 0, den1 = 0, den2 = 0, den3 = 0;
    float sa0 = 0, sa1 = 0, sa2 = 0, sa3 = 0;

    for (int base = beg; base < end; base += 32) {
        int i = base + lane;
        float p0 = 0, p1 = 0, p2 = 0, p3 = 0;
        int s = 0;
        if (i < end) {
            s = g_csrc[i];
            float4 ae = aeC[i];
            float4 as = *(const float4*)(g_as + (size_t)s * 4);
            sa0 += ae.x; sa1 += ae.y; sa2 += ae.z; sa3 += ae.w;
            p0 = __expf(lrelu(as.x + adv.x + ae.x));
            p1 = __expf(lrelu(as.y + adv.y + ae.y));
            p2 = __expf(lrelu(as.z + adv.z + ae.z));
            p3 = __expf(lrelu(as.w + adv.w + ae.w));
            den0 += p0; den1 += p1; den2 += p2; den3 += p3;
        }
        sp[wrp][lane] = make_float4(p0, p1, p2, p3);
        si[wrp][lane] = s;
        __syncwarp();
        int cnt = min(32, end - base);
        #pragma unroll 4
        for (int jj = 0; jj < cnt; jj++) {
            int ss = si[wrp][jj];
            float q = ((const float*)&sp[wrp][jj])[h];
            const float4* xr = (const float4*)(g_xs + (size_t)ss * HC + f0);
            float4 xa = xr[0], xb = xr[1];
            acc[0] = fmaf(q, xa.x, acc[0]); acc[1] = fmaf(q, xa.y, acc[1]);
            acc[2] = fmaf(q, xa.z, acc[2]); acc[3] = fmaf(q, xa.w, acc[3]);
            acc[4] = fmaf(q, xb.x, acc[4]); acc[5] = fmaf(q, xb.y, acc[5]);
            acc[6] = fmaf(q, xb.z, acc[6]); acc[7] = fmaf(q, xb.w, acc[7]);
        }
        __syncwarp();
    }
    #pragma unroll
    for (int o = 16; o; o >>= 1) {
        den0 += __shfl_xor_sync(0xffffffffu, den0, o);
        den1 += __shfl_xor_sync(0xffffffffu, den1, o);
        den2 += __shfl_xor_sync(0xffffffffu, den2, o);
        den3 += __shfl_xor_sync(0xffffffffu, den3, o);
        sa0 += __shfl_xor_sync(0xffffffffu, sa0, o);
        sa1 += __shfl_xor_sync(0xffffffffu, sa1, o);
        sa2 += __shfl_xor_sync(0xffffffffu, sa2, o);
        sa3 += __shfl_xor_sync(0xffffffffu, sa3, o);
    }
    int deg = end - beg;
    float invd = 1.0f / fmaxf((float)deg, 1.0f);
    float4 asn = *(const float4*)(g_as + (size_t)w * 4);
    float ps0 = __expf(lrelu(asn.x + adv.x + sa0 * invd));
    float ps1 = __expf(lrelu(asn.y + adv.y + sa1 * invd));
    float ps2 = __expf(lrelu(asn.z + adv.z + sa2 * invd));
    float ps3 = __expf(lrelu(asn.w + adv.w + sa3 * invd));
    den0 += ps0 + 1e-16f; den1 += ps1 + 1e-16f;
    den2 += ps2 + 1e-16f; den3 += ps3 + 1e-16f;
    const float4* xn = (const float4*)(g_xs + (size_t)w * HC + f0);
    float4 xa = xn[0], xb = xn[1];
    float psh = (h == 0) ? ps0 : (h == 1) ? ps1 : (h == 2) ? ps2 : ps3;
    acc[0] = fmaf(psh, xa.x, acc[0]); acc[1] = fmaf(psh, xa.y, acc[1]);
    acc[2] = fmaf(psh, xa.z, acc[2]); acc[3] = fmaf(psh, xa.w, acc[3]);
    acc[4] = fmaf(psh, xb.x, acc[4]); acc[5] = fmaf(psh, xb.y, acc[5]);
    acc[6] = fmaf(psh, xb.z, acc[6]); acc[7] = fmaf(psh, xb.w, acc[7]);
    float denh = (h == 0) ? den0 : (h == 1) ? den1 : (h == 2) ? den2 : den3;
    float r = 1.0f / denh;
    float4 b0 = *(const float4*)(bias + f0);
    float4 b1 = *(const float4*)(bias + f0 + 4);
    float* op = g_hpre + (size_t)w * HC + f0;
    *(float4*)(op)     = make_float4(fmaf(acc[0], r, b0.x), fmaf(acc[1], r, b0.y),
                                     fmaf(acc[2], r, b0.z), fmaf(acc[3], r, b0.w));
    *(float4*)(op + 4) = make_float4(fmaf(acc[4], r, b1.x), fmaf(acc[5], r, b1.y),
                                     fmaf(acc[6], r, b1.z), fmaf(acc[7], r, b1.w));
}

// ---------------- BN batch stats (sum, sumsq per column) ----------------
__global__ void k_stats(int off) {
    int c = threadIdx.x;    // 256
    int rows = (NN + gridDim.x - 1) / gridDim.x;
    int r0 = blockIdx.x * rows, r1 = min(r0 + rows, NN);
    float s = 0.f, s2 = 0.f;
    for (int r = r0; r < r1; r++) {
        float v = g_hpre[(size_t)r * HC + c];
        s += v;
        s2 = fmaf(v, v, s2);
    }
    atomicAdd(&g_stats[off + c], s);
    atomicAdd(&g_stats[off + 256 + c], s2);
}

// layer1 BN -> per-column scale/shift (consumed by GEMM2 A-load)
__global__ void k_bnprep(const float* __restrict__ g, const float* __restrict__ be) {
    int c = threadIdx.x;
    const float invN = 1.0f / NN;
    float mu = g_stats[c] * invN;
    float var = g_stats[256 + c] * invN - mu * mu;
    float sc = g[c] * rsqrtf(var + 1e-5f);
    g_bnsc[c] = sc;
    g_bnsh[c] = be[c] - sc * mu;
}

// ---------------- final: out[n] = relu(BN(hpre2)) . wout + bout ----------------
__global__ void k_final(const float* __restrict__ g, const float* __restrict__ be,
                        const float* __restrict__ wout, const float* __restrict__ bout,
                        float* __restrict__ out) {
    int w = (blockIdx.x * blockDim.x + threadIdx.x) >> 5;
    if (w >= NN) return;
    int lane = threadIdx.x & 31;
    const float invN = 1.0f / NN;
    float s = 0.f;
    #pragma unroll
    for (int j = 0; j < 8; j++) {
        int f = lane + 32 * j;
        float mu = g_stats[512 + f] * invN;
        float var = g_stats[768 + f] * invN - mu * mu;
        float sc = g[f] * rsqrtf(var + 1e-5f);
        float v = fmaxf(sc * (g_hpre[(size_t)w * HC + f] - mu) + be[f], 0.f);
        s = fmaf(v, wout[f], s);
    }
    #pragma unroll
    for (int o = 16; o; o >>= 1) s += __shfl_xor_sync(0xffffffffu, s, o);
    if (lane == 0) out[w] = s + bout[0];
}

// ---------------- launch ----------------
extern "C" void kernel_launch(void* const* d_in, const int* in_sizes, int n_in,
                              void* d_out, int out_size) {
    const float* x     = (const float*)d_in[0];
    const int*   esrc  = (const int*)d_in[1];
    const int*   edst  = (const int*)d_in[2];
    const float* eattr = (const float*)d_in[3];
    const float* W1    = (const float*)d_in[4];
    const float* atts1 = (const float*)d_in[5];
    const float* attd1 = (const float*)d_in[6];
    const float* We1   = (const float*)d_in[7];
    const float* atte1 = (const float*)d_in[8];
    const float* b1    = (const float*)d_in[9];
    const float* g1    = (const float*)d_in[10];
    const float* be1   = (const float*)d_in[11];
    const float* W2    = (const float*)d_in[12];
    const float* atts2 = (const float*)d_in[13];
    const float* attd2 = (const float*)d_in[14];
    const float* We2   = (const float*)d_in[15];
    const float* atte2 = (const float*)d_in[16];
    const float* b2    = (const float*)d_in[17];
    const float* g2    = (const float*)d_in[18];
    const float* be2   = (const float*)d_in[19];
    const float* Wout  = (const float*)d_in[20];
    const float* bout  = (const float*)d_in[21];
    float* out = (float*)d_out;

    const int EB = (EE + 255) / 256;
    const int NB = (NN + 255) / 256;
    const int WB = NN / 8;                 // warp-per-node kernels (256 thr)
    dim3 gg(2, (NN + 127) / 128);

    // setup
    k_zero<<<NB, 256>>>();
    k_ve<<<1, 128>>>(We1, atte1, We2, atte2);
    k_prepW<<<256, 64>>>(W1, 64, 0);
    k_prepW<<<256, 256>>>(W2, 256, 1);
    k_edge<<<EB, 256>>>(eattr, edst);
    k_scan1<<<NB, 256>>>();
    k_scan2<<<1, 256>>>(NB);
    k_scan3<<<NB, 256>>>();
    k_fill<<<EB, 256>>>(esrc, edst);

    // layer 1 (attdot fused into GEMM epilogue)
    k_gemm<<<gg, 256>>>(x, NN, 64, 0, 0, atts1, attd1);
    k_agg<<<WB, 256>>>(0, b1);
    k_stats<<<256, 256>>>(0);
    k_bnprep<<<1, 256>>>(g1, be1);

    // layer 2 (BN-ReLU of layer1 fused into GEMM A-load)
    k_gemm<<<gg, 256>>>(nullptr, NN, 256, 1, 1, atts2, attd2);
    k_agg<<<WB, 256>>>(1, b2);
    k_stats<<<256, 256>>>(512);

    // output head
    k_final<<<WB, 256>>>(g2, be2, Wout, bout, out);
}

// round 5
// speedup vs baseline: 1.4938x; 1.1164x over previous
#include <cuda_runtime.h>
#include <cuda_bf16.h>
#include <cuda_fp16.h>

#define NN 50000
#define EE 800000
#define HC 256

// ---------------- scratch (device globals; no allocation allowed) ----------------
__device__ __align__(16) __half g_xsh[NN * HC];  // xs of current layer, fp16
__device__ float g_hpre[NN * HC];   // aggregated pre-BN output (fp32)
__device__ float g_as[NN * 4];
__device__ float g_ad[NN * 4];
__device__ float g_ae1[EE * 4];     // edge order
__device__ float g_ae2[EE * 4];
__device__ float g_ae1c[EE * 4];    // CSR order
__device__ float g_ae2c[EE * 4];
__device__ int   g_deg[NN];
__device__ int   g_offs[NN + 1];
__device__ int   g_cursor[NN];
__device__ int   g_bsum[256];
__device__ int   g_bbase[257];
__device__ int   g_csrc[EE];
__device__ float g_ve1[64];         // [16,4]
__device__ float g_ve2[64];
__device__ float g_stats[1024];     // layer1: [0,512), layer2: [512,1024)
__device__ float g_bnsc[256];       // layer1 BN scale (fused into GEMM2 A-load)
__device__ float g_bnsh[256];       // layer1 BN shift
// W pre-transposed [n][k], bf16 hi/lo planes, per layer
__device__ __align__(16) unsigned short g_WtH[2][256 * 256];
__device__ __align__(16) unsigned short g_WtL[2][256 * 256];

__device__ __forceinline__ float lrelu(float x) { return fmaxf(x, 0.2f * x); }

__device__ __forceinline__ void split_pk(float x0, float x1, unsigned& h, unsigned& l) {
    __nv_bfloat16 h0 = __float2bfloat16_rn(x0), h1 = __float2bfloat16_rn(x1);
    float r0 = x0 - __bfloat162float(h0), r1 = x1 - __bfloat162float(h1);
    __nv_bfloat16 l0 = __float2bfloat16_rn(r0), l1 = __float2bfloat16_rn(r1);
    h = (unsigned)__bfloat16_as_ushort(h0) | ((unsigned)__bfloat16_as_ushort(h1) << 16);
    l = (unsigned)__bfloat16_as_ushort(l0) | ((unsigned)__bfloat16_as_ushort(l1) << 16);
}

#define MMA_BF16(C, A0, A1, A2, A3, B0, B1)                                      \
    asm volatile("mma.sync.aligned.m16n8k16.row.col.f32.bf16.bf16.f32 "          \
                 "{%0,%1,%2,%3}, {%4,%5,%6,%7}, {%8,%9}, {%0,%1,%2,%3};\n"       \
                 : "+f"((C)[0]), "+f"((C)[1]), "+f"((C)[2]), "+f"((C)[3])        \
                 : "r"(A0), "r"(A1), "r"(A2), "r"(A3), "r"(B0), "r"(B1))

// ---------------- setup kernels ----------------
__global__ void k_zero() {
    int i = blockIdx.x * blockDim.x + threadIdx.x;
    if (i < NN) g_deg[i] = 0;
    if (i < 1024) g_stats[i] = 0.f;
}

// Ve[j][h] = sum_c We[j, h*64+c] * atte[h, c]
__global__ void k_ve(const float* __restrict__ We1, const float* __restrict__ at1,
                     const float* __restrict__ We2, const float* __restrict__ at2) {
    int t = threadIdx.x;            // 128 threads
    int which = t >> 6;
    int u = t & 63;
    int j = u >> 2, h = u & 3;
    const float* We = which ? We2 : We1;
    const float* at = which ? at2 : at1;
    float s = 0.f;
    #pragma unroll 8
    for (int c = 0; c < 64; c++) s += We[j * HC + h * 64 + c] * at[h * 64 + c];
    if (which) g_ve2[u] = s; else g_ve1[u] = s;
}

// W[K,256] fp32 -> Wt[n][k] bf16 hi/lo planes
__global__ void k_prepW(const float* __restrict__ W, int K, int layer) {
    int n = blockIdx.x;
    int k = threadIdx.x;
    if (k >= K) return;
    float x = W[(size_t)k * 256 + n];
    __nv_bfloat16 h = __float2bfloat16_rn(x);
    float lo = x - __bfloat162float(h);
    __nv_bfloat16 l = __float2bfloat16_rn(lo);
    g_WtH[layer][n * K + k] = __bfloat16_as_ushort(h);
    g_WtL[layer][n * K + k] = __bfloat16_as_ushort(l);
}

// per-edge a_e for both layers + degree histogram
__global__ void k_edge(const float* __restrict__ eattr, const int* __restrict__ dst) {
    int e = blockIdx.x * blockDim.x + threadIdx.x;
    if (e >= EE) return;
    const float4* p = (const float4*)(eattr + (size_t)e * 16);
    float4 a = p[0], b = p[1], c = p[2], d = p[3];
    float v[16] = {a.x,a.y,a.z,a.w, b.x,b.y,b.z,b.w, c.x,c.y,c.z,c.w, d.x,d.y,d.z,d.w};
    float o1[4] = {0,0,0,0}, o2[4] = {0,0,0,0};
    #pragma unroll
    for (int j = 0; j < 16; j++) {
        #pragma unroll
        for (int h = 0; h < 4; h++) {
            o1[h] += v[j] * g_ve1[j * 4 + h];
            o2[h] += v[j] * g_ve2[j * 4 + h];
        }
    }
    *(float4*)(g_ae1 + (size_t)e * 4) = make_float4(o1[0], o1[1], o1[2], o1[3]);
    *(float4*)(g_ae2 + (size_t)e * 4) = make_float4(o2[0], o2[1], o2[2], o2[3]);
    atomicAdd(&g_deg[dst[e]], 1);
}

// ------------- 3-kernel exclusive scan of deg -> offs, cursor -------------
__global__ void k_scan1() {
    __shared__ int sh[256];
    int b = blockIdx.x, t = threadIdx.x;
    int i = b * 256 + t;
    sh[t] = (i < NN) ? g_deg[i] : 0;
    __syncthreads();
    for (int o = 128; o; o >>= 1) { if (t < o) sh[t] += sh[t + o]; __syncthreads(); }
    if (t == 0) g_bsum[b] = sh[0];
}

__global__ void k_scan2(int nb) {
    __shared__ int sh[256];
    int t = threadIdx.x;
    sh[t] = (t < nb) ? g_bsum[t] : 0;
    __syncthreads();
    for (int o = 1; o < 256; o <<= 1) {
        int v = (t >= o) ? sh[t - o] : 0;
        __syncthreads();
        sh[t] += v;
        __syncthreads();
    }
    g_bbase[t + 1] = sh[t];
    if (t == 0) { g_bbase[0] = 0; g_offs[NN] = EE; }
}

__global__ void k_scan3() {
    __shared__ int sh[256];
    int b = blockIdx.x, t = threadIdx.x;
    int i = b * 256 + t;
    int d = (i < NN) ? g_deg[i] : 0;
    sh[t] = d;
    __syncthreads();
    for (int o = 1; o < 256; o <<= 1) {
        int v = (t >= o) ? sh[t - o] : 0;
        __syncthreads();
        sh[t] += v;
        __syncthreads();
    }
    if (i < NN) {
        int off = g_bbase[b] + sh[t] - d;
        g_offs[i] = off;
        g_cursor[i] = off;
    }
}

// fill CSR: src ids + a_e permuted to CSR order
__global__ void k_fill(const int* __restrict__ src, const int* __restrict__ dst) {
    int e = blockIdx.x * blockDim.x + threadIdx.x;
    if (e >= EE) return;
    int pos = atomicAdd(&g_cursor[dst[e]], 1);
    g_csrc[pos] = src[e];
    ((float4*)g_ae1c)[pos] = ((const float4*)g_ae1)[e];
    ((float4*)g_ae2c)[pos] = ((const float4*)g_ae2)[e];
}

// ---------------- tensor-core GEMM: C[M,256] = A[M,K] @ W, bf16 3-term split ----
// BM=128 BN=128 BK=16, 8 warps (2m x 4n), warp tile 64x32, mma m16n8k16.
// Fused: optional BN-ReLU on A-load (layer2), attdot epilogue, fp16 C store.
__global__ void __launch_bounds__(256, 2)
k_gemm(const float* __restrict__ Aext, int M, int K, int layer, int bnflag,
       const float* __restrict__ atts, const float* __restrict__ attd) {
    const float* A = Aext ? Aext : g_hpre;
    __shared__ unsigned sAh[128 * 12], sAl[128 * 12];
    __shared__ unsigned sBh[128 * 12], sBl[128 * 12];
    __shared__ float2 sred[4][128];
    int tid = threadIdx.x;
    int lane = tid & 31, wid = tid >> 5;
    int wm = (wid >> 2) * 64, wn = (wid & 3) * 32;
    int rowBlk = blockIdx.y * 128, colBlk = blockIdx.x * 128;

    int ar = tid >> 1;
    int ak = (tid & 1) * 8;
    bool aval = (rowBlk + ar) < M;
    const float* Ap = A + (size_t)(rowBlk + ar) * K + ak;
    int bn_ = tid & 127;
    int bsel = tid >> 7;
    const unsigned short* Bp =
        (bsel ? g_WtL[layer] : g_WtH[layer]) + (size_t)(colBlk + bn_) * K;

    float c[4][4][4];
    #pragma unroll
    for (int mt = 0; mt < 4; mt++)
        #pragma unroll
        for (int nt = 0; nt < 4; nt++)
            #pragma unroll
            for (int q = 0; q < 4; q++) c[mt][nt][q] = 0.f;

    int nch = K >> 4;
    float av[8];
    uint4 bq0, bq1;
    {
        float4 u = aval ? *(const float4*)(Ap) : make_float4(0, 0, 0, 0);
        float4 v = aval ? *(const float4*)(Ap + 4) : make_float4(0, 0, 0, 0);
        av[0]=u.x; av[1]=u.y; av[2]=u.z; av[3]=u.w;
        av[4]=v.x; av[5]=v.y; av[6]=v.z; av[7]=v.w;
        bq0 = ((const uint4*)(Bp))[0];
        bq1 = ((const uint4*)(Bp))[1];
    }

    for (int ch = 0; ch < nch; ch++) {
        if (bnflag && aval) {
            int kk = ch * 16 + ak;
            #pragma unroll
            for (int j = 0; j < 8; j++)
                av[j] = fmaxf(fmaf(g_bnsc[kk + j], av[j], g_bnsh[kk + j]), 0.f);
        }
        {
            unsigned h0, h1, h2, h3, l0, l1, l2, l3;
            split_pk(av[0], av[1], h0, l0);
            split_pk(av[2], av[3], h1, l1);
            split_pk(av[4], av[5], h2, l2);
            split_pk(av[6], av[7], h3, l3);
            int base = ar * 12 + (ak >> 1);
            *(uint4*)(sAh + base) = make_uint4(h0, h1, h2, h3);
            *(uint4*)(sAl + base) = make_uint4(l0, l1, l2, l3);
            unsigned* sB = bsel ? sBl : sBh;
            int bb = bn_ * 12;
            *(uint4*)(sB + bb) = bq0;
            *(uint4*)(sB + bb + 4) = bq1;
        }
        __syncthreads();
        if (ch + 1 < nch) {
            const float* Ap2 = Ap + (ch + 1) * 16;
            float4 u = aval ? *(const float4*)(Ap2) : make_float4(0, 0, 0, 0);
            float4 v = aval ? *(const float4*)(Ap2 + 4) : make_float4(0, 0, 0, 0);
            av[0]=u.x; av[1]=u.y; av[2]=u.z; av[3]=u.w;
            av[4]=v.x; av[5]=v.y; av[6]=v.z; av[7]=v.w;
            const uint4* Bc = (const uint4*)(Bp + (ch + 1) * 16);
            bq0 = Bc[0];
            bq1 = Bc[1];
        }
        unsigned bh0[4], bh1[4], bl0[4], bl1[4];
        #pragma unroll
        for (int nt = 0; nt < 4; nt++) {
            int nb = (wn + nt * 8 + (lane >> 2)) * 12 + (lane & 3);
            bh0[nt] = sBh[nb]; bh1[nt] = sBh[nb + 4];
            bl0[nt] = sBl[nb]; bl1[nt] = sBl[nb + 4];
        }
        #pragma unroll
        for (int mt = 0; mt < 4; mt++) {
            int ab = (wm + mt * 16 + (lane >> 2)) * 12 + (lane & 3);
            unsigned ah0 = sAh[ab], ah1 = sAh[ab + 96];
            unsigned ah2 = sAh[ab + 4], ah3 = sAh[ab + 100];
            unsigned al0 = sAl[ab], al1 = sAl[ab + 96];
            unsigned al2 = sAl[ab + 4], al3 = sAl[ab + 100];
            #pragma unroll
            for (int nt = 0; nt < 4; nt++) {
                MMA_BF16(c[mt][nt], ah0, ah1, ah2, ah3, bh0[nt], bh1[nt]);
                MMA_BF16(c[mt][nt], ah0, ah1, ah2, ah3, bl0[nt], bl1[nt]);
                MMA_BF16(c[mt][nt], al0, al1, al2, al3, bh0[nt], bh1[nt]);
            }
        }
        __syncthreads();
    }

    // epilogue: write C as fp16 (only consumer is the agg gather)
    #pragma unroll
    for (int mt = 0; mt < 4; mt++) {
        int r0 = rowBlk + wm + mt * 16 + (lane >> 2);
        #pragma unroll
        for (int nt = 0; nt < 4; nt++) {
            int col = colBlk + wn + nt * 8 + (lane & 3) * 2;
            if (r0 < M)
                *(__half2*)(g_xsh + (size_t)r0 * 256 + col) =
                    __floats2half2_rn(c[mt][nt][0], c[mt][nt][1]);
            if (r0 + 8 < M)
                *(__half2*)(g_xsh + (size_t)(r0 + 8) * 256 + col) =
                    __floats2half2_rn(c[mt][nt][2], c[mt][nt][3]);
        }
    }
    // fused attdot: partial dots per n-warp -> smem -> reduce -> g_as/g_ad (fp32 frags)
    float sv[4][2], dv[4][2];
    #pragma unroll
    for (int nt = 0; nt < 4; nt++)
        #pragma unroll
        for (int q = 0; q < 2; q++) {
            int col = colBlk + wn + nt * 8 + (lane & 3) * 2 + q;
            sv[nt][q] = atts[col];
            dv[nt][q] = attd[col];
        }
    #pragma unroll
    for (int mt = 0; mt < 4; mt++) {
        #pragma unroll
        for (int half = 0; half < 2; half++) {
            float ss = 0.f, dd = 0.f;
            #pragma unroll
            for (int nt = 0; nt < 4; nt++) {
                #pragma unroll
                for (int q = 0; q < 2; q++) {
                    ss = fmaf(c[mt][nt][half * 2 + q], sv[nt][q], ss);
                    dd = fmaf(c[mt][nt][half * 2 + q], dv[nt][q], dd);
                }
            }
            ss += __shfl_xor_sync(0xffffffffu, ss, 1);
            ss += __shfl_xor_sync(0xffffffffu, ss, 2);
            dd += __shfl_xor_sync(0xffffffffu, dd, 1);
            dd += __shfl_xor_sync(0xffffffffu, dd, 2);
            if ((lane & 3) == 0)
                sred[wid & 3][wm + mt * 16 + half * 8 + (lane >> 2)] =
                    make_float2(ss, dd);
        }
    }
    __syncthreads();
    {
        int row = tid >> 1, hl = tid & 1;
        int r = rowBlk + row;
        if (r < M) {
            float2 aa = sred[2 * hl][row], bb = sred[2 * hl + 1][row];
            int hidx = (colBlk >> 6) + hl;
            g_as[r * 4 + hidx] = aa.x + bb.x;
            g_ad[r * 4 + hidx] = aa.y + bb.y;
        }
    }
}

// ---------------- GAT aggregation: single pass, warp per dst node.
// fp16 row gather: one LDG.128 per edge per lane; fp32 accumulation. --------
__global__ void __launch_bounds__(256) k_agg(int layer, const float* __restrict__ bias) {
    __shared__ float4 sp[8][32];
    __shared__ int    si[8][32];
    int w = (blockIdx.x * blockDim.x + threadIdx.x) >> 5;
    if (w >= NN) return;
    int lane = threadIdx.x & 31;
    int wrp = threadIdx.x >> 5;
    const float4* aeC = (const float4*)(layer ? g_ae2c : g_ae1c);
    int beg = g_offs[w], end = g_offs[w + 1];
    float4 adv = *(const float4*)(g_ad + (size_t)w * 4);
    int h = lane >> 3;
    int f0 = lane * 8;
    float acc[8] = {0, 0, 0, 0, 0, 0, 0, 0};
    float den0 = 0, den1 = 0, den2 = 0, den3 = 0;
    float sa0 = 0, sa1 = 0, sa2 = 0, sa3 = 0;

    for (int base = beg; base < end; base += 32) {
        int i = base + lane;
        float p0 = 0, p1 = 0, p2 = 0, p3 = 0;
        int s = 0;
        if (i < end) {
            s = g_csrc[i];
            float4 ae = aeC[i];
            float4 as = *(const float4*)(g_as + (size_t)s * 4);
            sa0 += ae.x; sa1 += ae.y; sa2 += ae.z; sa3 += ae.w;
            p0 = __expf(lrelu(as.x + adv.x + ae.x));
            p1 = __expf(lrelu(as.y + adv.y + ae.y));
            p2 = __expf(lrelu(as.z + adv.z + ae.z));
            p3 = __expf(lrelu(as.w + adv.w + ae.w));
            den0 += p0; den1 += p1; den2 += p2; den3 += p3;
        }
        sp[wrp][lane] = make_float4(p0, p1, p2, p3);
        si[wrp][lane] = s;
        __syncwarp();
        int cnt = min(32, end - base);
        #pragma unroll 4
        for (int jj = 0; jj < cnt; jj++) {
            int ss = si[wrp][jj];
            float q = ((const float*)&sp[wrp][jj])[h];
            uint4 xv = *(const uint4*)(g_xsh + (size_t)ss * HC + f0);
            float2 x0 = __half22float2(*(__half2*)&xv.x);
            float2 x1 = __half22float2(*(__half2*)&xv.y);
            float2 x2 = __half22float2(*(__half2*)&xv.z);
            float2 x3 = __half22float2(*(__half2*)&xv.w);
            acc[0] = fmaf(q, x0.x, acc[0]); acc[1] = fmaf(q, x0.y, acc[1]);
            acc[2] = fmaf(q, x1.x, acc[2]); acc[3] = fmaf(q, x1.y, acc[3]);
            acc[4] = fmaf(q, x2.x, acc[4]); acc[5] = fmaf(q, x2.y, acc[5]);
            acc[6] = fmaf(q, x3.x, acc[6]); acc[7] = fmaf(q, x3.y, acc[7]);
        }
        __syncwarp();
    }
    #pragma unroll
    for (int o = 16; o; o >>= 1) {
        den0 += __shfl_xor_sync(0xffffffffu, den0, o);
        den1 += __shfl_xor_sync(0xffffffffu, den1, o);
        den2 += __shfl_xor_sync(0xffffffffu, den2, o);
        den3 += __shfl_xor_sync(0xffffffffu, den3, o);
        sa0 += __shfl_xor_sync(0xffffffffu, sa0, o);
        sa1 += __shfl_xor_sync(0xffffffffu, sa1, o);
        sa2 += __shfl_xor_sync(0xffffffffu, sa2, o);
        sa3 += __shfl_xor_sync(0xffffffffu, sa3, o);
    }
    int deg = end - beg;
    float invd = 1.0f / fmaxf((float)deg, 1.0f);
    float4 asn = *(const float4*)(g_as + (size_t)w * 4);
    float ps0 = __expf(lrelu(asn.x + adv.x + sa0 * invd));
    float ps1 = __expf(lrelu(asn.y + adv.y + sa1 * invd));
    float ps2 = __expf(lrelu(asn.z + adv.z + sa2 * invd));
    float ps3 = __expf(lrelu(asn.w + adv.w + sa3 * invd));
    den0 += ps0 + 1e-16f; den1 += ps1 + 1e-16f;
    den2 += ps2 + 1e-16f; den3 += ps3 + 1e-16f;
    {
        uint4 xv = *(const uint4*)(g_xsh + (size_t)w * HC + f0);
        float2 x0 = __half22float2(*(__half2*)&xv.x);
        float2 x1 = __half22float2(*(__half2*)&xv.y);
        float2 x2 = __half22float2(*(__half2*)&xv.z);
        float2 x3 = __half22float2(*(__half2*)&xv.w);
        float psh = (h == 0) ? ps0 : (h == 1) ? ps1 : (h == 2) ? ps2 : ps3;
        acc[0] = fmaf(psh, x0.x, acc[0]); acc[1] = fmaf(psh, x0.y, acc[1]);
        acc[2] = fmaf(psh, x1.x, acc[2]); acc[3] = fmaf(psh, x1.y, acc[3]);
        acc[4] = fmaf(psh, x2.x, acc[4]); acc[5] = fmaf(psh, x2.y, acc[5]);
        acc[6] = fmaf(psh, x3.x, acc[6]); acc[7] = fmaf(psh, x3.y, acc[7]);
    }
    float denh = (h == 0) ? den0 : (h == 1) ? den1 : (h == 2) ? den2 : den3;
    float r = 1.0f / denh;
    float4 b0 = *(const float4*)(bias + f0);
    float4 b1 = *(const float4*)(bias + f0 + 4);
    float* op = g_hpre + (size_t)w * HC + f0;
    *(float4*)(op)     = make_float4(fmaf(acc[0], r, b0.x), fmaf(acc[1], r, b0.y),
                                     fmaf(acc[2], r, b0.z), fmaf(acc[3], r, b0.w));
    *(float4*)(op + 4) = make_float4(fmaf(acc[4], r, b1.x), fmaf(acc[5], r, b1.y),
                                     fmaf(acc[6], r, b1.z), fmaf(acc[7], r, b1.w));
}

// ---------------- BN batch stats (sum, sumsq per column) ----------------
__global__ void k_stats(int off) {
    int c = threadIdx.x;    // 256
    int rows = (NN + gridDim.x - 1) / gridDim.x;
    int r0 = blockIdx.x * rows, r1 = min(r0 + rows, NN);
    float s = 0.f, s2 = 0.f;
    for (int r = r0; r < r1; r++) {
        float v = g_hpre[(size_t)r * HC + c];
        s += v;
        s2 = fmaf(v, v, s2);
    }
    atomicAdd(&g_stats[off + c], s);
    atomicAdd(&g_stats[off + 256 + c], s2);
}

// layer1 BN -> per-column scale/shift (consumed by GEMM2 A-load)
__global__ void k_bnprep(const float* __restrict__ g, const float* __restrict__ be) {
    int c = threadIdx.x;
    const float invN = 1.0f / NN;
    float mu = g_stats[c] * invN;
    float var = g_stats[256 + c] * invN - mu * mu;
    float sc = g[c] * rsqrtf(var + 1e-5f);
    g_bnsc[c] = sc;
    g_bnsh[c] = be[c] - sc * mu;
}

// ---------------- final: out[n] = relu(BN(hpre2)) . wout + bout ----------------
__global__ void k_final(const float* __restrict__ g, const float* __restrict__ be,
                        const float* __restrict__ wout, const float* __restrict__ bout,
                        float* __restrict__ out) {
    int w = (blockIdx.x * blockDim.x + threadIdx.x) >> 5;
    if (w >= NN) return;
    int lane = threadIdx.x & 31;
    const float invN = 1.0f / NN;
    float s = 0.f;
    #pragma unroll
    for (int j = 0; j < 8; j++) {
        int f = lane + 32 * j;
        float mu = g_stats[512 + f] * invN;
        float var = g_stats[768 + f] * invN - mu * mu;
        float sc = g[f] * rsqrtf(var + 1e-5f);
        float v = fmaxf(sc * (g_hpre[(size_t)w * HC + f] - mu) + be[f], 0.f);
        s = fmaf(v, wout[f], s);
    }
    #pragma unroll
    for (int o = 16; o; o >>= 1) s += __shfl_xor_sync(0xffffffffu, s, o);
    if (lane == 0) out[w] = s + bout[0];
}

// ---------------- launch ----------------
extern "C" void kernel_launch(void* const* d_in, const int* in_sizes, int n_in,
                              void* d_out, int out_size) {
    const float* x     = (const float*)d_in[0];
    const int*   esrc  = (const int*)d_in[1];
    const int*   edst  = (const int*)d_in[2];
    const float* eattr = (const float*)d_in[3];
    const float* W1    = (const float*)d_in[4];
    const float* atts1 = (const float*)d_in[5];
    const float* attd1 = (const float*)d_in[6];
    const float* We1   = (const float*)d_in[7];
    const float* atte1 = (const float*)d_in[8];
    const float* b1    = (const float*)d_in[9];
    const float* g1    = (const float*)d_in[10];
    const float* be1   = (const float*)d_in[11];
    const float* W2    = (const float*)d_in[12];
    const float* atts2 = (const float*)d_in[13];
    const float* attd2 = (const float*)d_in[14];
    const float* We2   = (const float*)d_in[15];
    const float* atte2 = (const float*)d_in[16];
    const float* b2    = (const float*)d_in[17];
    const float* g2    = (const float*)d_in[18];
    const float* be2   = (const float*)d_in[19];
    const float* Wout  = (const float*)d_in[20];
    const float* bout  = (const float*)d_in[21];
    float* out = (float*)d_out;

    const int EB = (EE + 255) / 256;
    const int NB = (NN + 255) / 256;
    const int WB = NN / 8;                 // warp-per-node kernels (256 thr)
    dim3 gg(2, (NN + 127) / 128);

    // setup
    k_zero<<<NB, 256>>>();
    k_ve<<<1, 128>>>(We1, atte1, We2, atte2);
    k_prepW<<<256, 64>>>(W1, 64, 0);
    k_prepW<<<256, 256>>>(W2, 256, 1);
    k_edge<<<EB, 256>>>(eattr, edst);
    k_scan1<<<NB, 256>>>();
    k_scan2<<<1, 256>>>(NB);
    k_scan3<<<NB, 256>>>();
    k_fill<<<EB, 256>>>(esrc, edst);

    // layer 1 (attdot fused into GEMM epilogue)
    k_gemm<<<gg, 256>>>(x, NN, 64, 0, 0, atts1, attd1);
    k_agg<<<WB, 256>>>(0, b1);
    k_stats<<<256, 256>>>(0);
    k_bnprep<<<1, 256>>>(g1, be1);

    // layer 2 (BN-ReLU of layer1 fused into GEMM A-load)
    k_gemm<<<gg, 256>>>(nullptr, NN, 256, 1, 1, atts2, attd2);
    k_agg<<<WB, 256>>>(1, b2);
    k_stats<<<256, 256>>>(512);

    // output head
    k_final<<<WB, 256>>>(g2, be2, Wout, bout, out);
}